// round 1
// baseline (speedup 1.0000x reference)
#include <cuda_runtime.h>
#include <math.h>

#define NB 2
#define NQ 100
#define NC 256
#define NHW 64
#define NP 6
#define WSZ 7
#define WS2 49
#define NHD 8
#define HDD 32
#define NWIN 600            // Q*NP
#define NROWS 58800         // NB*NWIN*WS2
#define MPAD 58880          // 460*128 (GEMM M padding)
#define KD 256
#define NOUT3 768
#define OB_PER_B 7526400    // NHD*WS2*NWIN*HDD

// -------- scratch (static device globals; no runtime alloc allowed) --------
__device__ float g_xt[NB * NHW * NHW * NC];            // x transposed to (b,y,x,c)
__device__ float g_sp[(size_t)MPAD * KD];              // sampled features, rows 58800 real
__device__ float g_qkv[(size_t)MPAD * NOUT3];          // qkv projections
__device__ float g_o[(size_t)NB * OB_PER_B];           // attention out (scrambled-flat layout)
__device__ float g_ypre[NB * NWIN * NC];               // conv-reduced
__device__ float g_wpT[NC * NC];                       // w_proj transposed

// -------- K0: x (B,C,H,W) -> xt (B,H,W,C) --------
__global__ void k_transpose_x(const float* __restrict__ x) {
    int idx = blockIdx.x * 256 + threadIdx.x;          // enumerates xt layout
    if (idx >= NB * NHW * NHW * NC) return;
    int c = idx & 255;
    int rem = idx >> 8;                                 // b*4096 + pix
    int pix = rem & 4095;
    int b = rem >> 12;
    g_xt[idx] = x[(((size_t)b * NC + c) << 12) + pix];
}

// -------- K1: poly eval + bilinear sample -> sp[b,n,s,c] --------
__global__ void k_sample(const float* __restrict__ polys) {
    int j = blockIdx.x;                                // 0..58799 = ((b*600+n)*49+s)
    int t = threadIdx.x;                               // 0..63, 4 channels each (float4)
    int b = j / (NWIN * WS2);
    int r = j - b * (NWIN * WS2);
    int n = r / WS2;
    int s = r - n * WS2;
    int q = n / NP;
    int nid = n - q * NP;
    int m = nid * WS2 + s;                             // inverse of the grid reshape quirk
    int w = m / NP;
    int p = m - w * NP;

    const float* pc = polys + ((size_t)(b * NQ + q) * 2) * NP;
    float a = (float)p * 0.2f;                         // alpha = linspace(0,1,6)[p]
    float py = pc[0];
    #pragma unroll
    for (int i = 1; i < NP; i++) py = py * a + pc[i];  // Horner, coeffs high->low power
    float px = pc[NP];
    #pragma unroll
    for (int i = 1; i < NP; i++) px = px * a + pc[NP + i];
    py = 2.f * py - 1.f;
    px = 2.f * px - 1.f;

    int wy = w / WSZ, wx = w - wy * WSZ;
    float dy = (-4.0f + (float)wy * (7.0f / 6.0f)) * (2.0f / 64.0f);
    float dx = (-4.0f + (float)wx * (7.0f / 6.0f)) * (2.0f / 64.0f);
    float gy = py + dy, gx = px + dx;

    // reference quirk: fx from grid_y, fy from grid_x
    float fx = (gy + 1.f) * 0.5f * 63.f;
    float fy = (gx + 1.f) * 0.5f * 63.f;
    float x0f = floorf(fx), y0f = floorf(fy);
    float wx1 = fx - x0f, wy1 = fy - y0f;

    float vx0 = (x0f >= 0.f && x0f <= 63.f) ? 1.f : 0.f;
    float vx1 = (x0f + 1.f >= 0.f && x0f + 1.f <= 63.f) ? 1.f : 0.f;
    float vy0 = (y0f >= 0.f && y0f <= 63.f) ? 1.f : 0.f;
    float vy1 = (y0f + 1.f >= 0.f && y0f + 1.f <= 63.f) ? 1.f : 0.f;
    int xi0 = min(max((int)x0f, 0), 63);
    int xi1 = min(max((int)x0f + 1, 0), 63);
    int yi0 = min(max((int)y0f, 0), 63);
    int yi1 = min(max((int)y0f + 1, 0), 63);

    float w00 = (1.f - wy1) * (1.f - wx1) * vy0 * vx0;
    float w01 = (1.f - wy1) * wx1 * vy0 * vx1;
    float w10 = wy1 * (1.f - wx1) * vy1 * vx0;
    float w11 = wy1 * wx1 * vy1 * vx1;

    const float4* xt4 = (const float4*)g_xt;           // 64 float4 per pixel
    size_t pbase = (size_t)b * 4096;
    const float4* p00 = xt4 + (pbase + yi0 * 64 + xi0) * 64;
    const float4* p01 = xt4 + (pbase + yi0 * 64 + xi1) * 64;
    const float4* p10 = xt4 + (pbase + yi1 * 64 + xi0) * 64;
    const float4* p11 = xt4 + (pbase + yi1 * 64 + xi1) * 64;
    float4 v00 = p00[t], v01 = p01[t], v10 = p10[t], v11 = p11[t];
    float4 o;
    o.x = w00 * v00.x + w01 * v01.x + w10 * v10.x + w11 * v11.x;
    o.y = w00 * v00.y + w01 * v01.y + w10 * v10.y + w11 * v11.y;
    o.z = w00 * v00.z + w01 * v01.z + w10 * v10.z + w11 * v11.z;
    o.w = w00 * v00.w + w01 * v01.w + w10 * v10.w + w11 * v11.w;
    ((float4*)g_sp)[(size_t)j * 64 + t] = o;
}

// -------- K2: qkv = sp @ w_qkv^T + b_qkv  (M=MPAD, K=256, N=768) --------
__global__ void __launch_bounds__(256) k_qkv_gemm(const float* __restrict__ Wq,
                                                  const float* __restrict__ bq) {
    __shared__ float As[16][128];
    __shared__ float Bs[16][64];
    int bm = blockIdx.x * 128;
    int bn = blockIdx.y * 64;
    int tid = threadIdx.x;
    int ty = tid >> 4, tx = tid & 15;                  // 16x16 threads, 8x4 microtile
    float acc[8][4];
    #pragma unroll
    for (int i = 0; i < 8; i++)
        #pragma unroll
        for (int j2 = 0; j2 < 4; j2++) acc[i][j2] = 0.f;

    const int r0 = tid >> 2;
    const int kk4 = (tid & 3) * 4;

    for (int k0 = 0; k0 < KD; k0 += 16) {
        float4 a0 = *(const float4*)&g_sp[(size_t)(bm + r0) * KD + k0 + kk4];
        float4 a1 = *(const float4*)&g_sp[(size_t)(bm + 64 + r0) * KD + k0 + kk4];
        float4 bv = *(const float4*)&Wq[(size_t)(bn + r0) * KD + k0 + kk4];
        As[kk4 + 0][r0] = a0.x; As[kk4 + 1][r0] = a0.y;
        As[kk4 + 2][r0] = a0.z; As[kk4 + 3][r0] = a0.w;
        As[kk4 + 0][64 + r0] = a1.x; As[kk4 + 1][64 + r0] = a1.y;
        As[kk4 + 2][64 + r0] = a1.z; As[kk4 + 3][64 + r0] = a1.w;
        Bs[kk4 + 0][r0] = bv.x; Bs[kk4 + 1][r0] = bv.y;
        Bs[kk4 + 2][r0] = bv.z; Bs[kk4 + 3][r0] = bv.w;
        __syncthreads();
        #pragma unroll
        for (int kk = 0; kk < 16; kk++) {
            float4 aA = *(const float4*)&As[kk][ty * 8];
            float4 aB = *(const float4*)&As[kk][ty * 8 + 4];
            float4 bb = *(const float4*)&Bs[kk][tx * 4];
            float av[8] = {aA.x, aA.y, aA.z, aA.w, aB.x, aB.y, aB.z, aB.w};
            float bvv[4] = {bb.x, bb.y, bb.z, bb.w};
            #pragma unroll
            for (int i = 0; i < 8; i++)
                #pragma unroll
                for (int j2 = 0; j2 < 4; j2++) acc[i][j2] += av[i] * bvv[j2];
        }
        __syncthreads();
    }
    float4 bias4 = *(const float4*)&bq[bn + tx * 4];
    #pragma unroll
    for (int i = 0; i < 8; i++) {
        int row = bm + ty * 8 + i;
        float4 o;
        o.x = acc[i][0] + bias4.x; o.y = acc[i][1] + bias4.y;
        o.z = acc[i][2] + bias4.z; o.w = acc[i][3] + bias4.w;
        *(float4*)&g_qkv[(size_t)row * NOUT3 + bn + tx * 4] = o;
    }
}

// -------- K3: per-(b,h,n) windowed attention, store to scrambled-flat o --------
__global__ void __launch_bounds__(256) k_attn(const float* __restrict__ pos_bias) {
    int blk = blockIdx.x;                              // b*4800 + h*600 + n
    int b = blk / (NHD * NWIN);
    int r = blk - b * NHD * NWIN;
    int h = r / NWIN;
    int n = r - h * NWIN;

    __shared__ float qs[WS2][36];                      // padded rows (144B) for float4 reads
    __shared__ float ks[WS2][36];
    __shared__ float vs[WS2][32];
    __shared__ float S[WS2][WS2];
    __shared__ float pbs[WS2];
    int tid = threadIdx.x;
    if (tid < WS2) pbs[tid] = pos_bias[tid];

    size_t rowbase = (size_t)(b * NWIN + n) * WS2 * NOUT3 + h * HDD;
    for (int e = tid; e < WS2 * HDD; e += 256) {
        int sidx = e >> 5, d = e & 31;
        size_t rb = rowbase + (size_t)sidx * NOUT3 + d;
        qs[sidx][d] = g_qkv[rb];
        ks[sidx][d] = g_qkv[rb + 256];
        vs[sidx][d] = g_qkv[rb + 512];
    }
    __syncthreads();

    const float scale = 0.17677669529663687f;          // 1/sqrt(32)
    for (int e = tid; e < WS2 * WS2; e += 256) {
        int pp = e / WS2, cc = e - pp * WS2;
        const float4* q4 = (const float4*)qs[pp];
        const float4* k4 = (const float4*)ks[cc];
        float accv = 0.f;
        #pragma unroll
        for (int i = 0; i < 8; i++) {
            float4 qv = q4[i], kv = k4[i];
            accv += qv.x * kv.x + qv.y * kv.y + qv.z * kv.z + qv.w * kv.w;
        }
        S[pp][cc] = accv * scale + pbs[pp];
    }
    __syncthreads();

    if (tid < WS2) {
        float mx = -1e30f;
        #pragma unroll 7
        for (int c = 0; c < WS2; c++) mx = fmaxf(mx, S[tid][c]);
        float sum = 0.f;
        #pragma unroll 7
        for (int c = 0; c < WS2; c++) { float ev = __expf(S[tid][c] - mx); S[tid][c] = ev; sum += ev; }
        float inv = 1.f / sum;
        #pragma unroll 7
        for (int c = 0; c < WS2; c++) S[tid][c] *= inv;
    }
    __syncthreads();

    // o[b,h,n,p,d] stored at batch-flat offset h*940800 + p*19200 + n*32 + d
    size_t obase = (size_t)b * OB_PER_B + (size_t)h * (WS2 * NWIN * HDD) + (size_t)n * HDD;
    for (int e = tid; e < WS2 * (HDD / 4); e += 256) { // 392 work items
        int pp = e >> 3, d4 = (e & 7) * 4;
        float4 accv = {0.f, 0.f, 0.f, 0.f};
        #pragma unroll 7
        for (int c = 0; c < WS2; c++) {
            float sv = S[pp][c];
            float4 vv = *(const float4*)&vs[c][d4];
            accv.x += sv * vv.x; accv.y += sv * vv.y;
            accv.z += sv * vv.z; accv.w += sv * vv.w;
        }
        *(float4*)&g_o[obase + (size_t)pp * (NWIN * HDD) + d4] = accv;
    }
}

// -------- K4: conv reduce over scrambled s2 axis --------
__global__ void k_conv(const float* __restrict__ conv_w, const float* __restrict__ conv_b) {
    __shared__ float cw[WS2];
    int tid = threadIdx.x;
    if (tid < WS2) cw[tid] = conv_w[tid];
    __syncthreads();
    int idx = blockIdx.x * 256 + tid;                  // < 307200
    int b = idx / (NWIN * NC);
    int r = idx - b * (NWIN * NC);
    int n2 = r >> 8, c2 = r & 255;
    size_t base = (size_t)b * OB_PER_B + (size_t)n2 * (WS2 * NC) + c2;
    float accv = conv_b[0];
    #pragma unroll 7
    for (int s2 = 0; s2 < WS2; s2++) accv += cw[s2] * g_o[base + (size_t)s2 * NC];
    g_ypre[idx] = accv;
}

// -------- K5a: transpose w_proj --------
__global__ void k_wpt(const float* __restrict__ wp) {
    int idx = blockIdx.x * 256 + threadIdx.x;          // < 65536
    int k = idx >> 8, c = idx & 255;
    g_wpT[idx] = wp[c * NC + k];
}

// -------- K5b: y = ypre @ w_proj^T + b_proj (4 rows/block) --------
__global__ void __launch_bounds__(256) k_proj(const float* __restrict__ bp, float* __restrict__ out) {
    __shared__ float rowv[4][NC];
    int row0 = blockIdx.x * 4;
    int c = threadIdx.x;
    #pragma unroll
    for (int i = 0; i < 4; i++) rowv[i][c] = g_ypre[(size_t)(row0 + i) * NC + c];
    __syncthreads();
    float a0 = 0.f, a1 = 0.f, a2 = 0.f, a3 = 0.f;
    #pragma unroll 8
    for (int k = 0; k < NC; k++) {
        float wv = g_wpT[k * NC + c];
        a0 += rowv[0][k] * wv; a1 += rowv[1][k] * wv;
        a2 += rowv[2][k] * wv; a3 += rowv[3][k] * wv;
    }
    float bb = bp[c];
    out[(size_t)(row0 + 0) * NC + c] = a0 + bb;
    out[(size_t)(row0 + 1) * NC + c] = a1 + bb;
    out[(size_t)(row0 + 2) * NC + c] = a2 + bb;
    out[(size_t)(row0 + 3) * NC + c] = a3 + bb;
}

extern "C" void kernel_launch(void* const* d_in, const int* in_sizes, int n_in,
                              void* d_out, int out_size) {
    const float* x        = (const float*)d_in[0];
    const float* polys    = (const float*)d_in[1];
    const float* w_qkv    = (const float*)d_in[2];
    const float* b_qkv    = (const float*)d_in[3];
    const float* w_proj   = (const float*)d_in[4];
    const float* b_proj   = (const float*)d_in[5];
    const float* conv_w   = (const float*)d_in[6];
    const float* conv_b   = (const float*)d_in[7];
    const float* pos_bias = (const float*)d_in[8];
    float* out = (float*)d_out;

    k_transpose_x<<<(NB * NHW * NHW * NC + 255) / 256, 256>>>(x);
    k_sample<<<NROWS, 64>>>(polys);
    dim3 g2(MPAD / 128, NOUT3 / 64);
    k_qkv_gemm<<<g2, 256>>>(w_qkv, b_qkv);
    k_attn<<<NB * NHD * NWIN, 256>>>(pos_bias);
    k_conv<<<(NB * NWIN * NC) / 256, 256>>>(conv_w, conv_b);
    k_wpt<<<NC * NC / 256, 256>>>(w_proj);
    k_proj<<<NB * NWIN / 4, 256>>>(b_proj, out);
}

// round 4
// speedup vs baseline: 1.4648x; 1.4648x over previous
#include <cuda_runtime.h>
#include <cuda_bf16.h>
#include <cstdint>
#include <math.h>

#define NB 2
#define NQ 100
#define NC 256
#define NHW 64
#define NP 6
#define WSZ 7
#define WS2 49
#define NHD 8
#define HDD 32
#define NWIN 600            // Q*NP
#define NROWS 58800         // NB*NWIN*WS2
#define MPAD 58880          // 460*128 (GEMM M padding)
#define KD 256
#define NOUT3 768
#define OB_PER_B 7526400    // NHD*WS2*NWIN*HDD

// -------- scratch (static device globals; no runtime alloc allowed) --------
__device__ float g_xt[NB * NHW * NHW * NC];            // x transposed to (b,y,x,c)
__device__ __nv_bfloat16 g_ahi[(size_t)MPAD * KD];     // sampled features hi (bf16)
__device__ __nv_bfloat16 g_alo[(size_t)MPAD * KD];     // sampled features lo (bf16)
__device__ __nv_bfloat16 g_bhi[NOUT3 * KD];            // w_qkv hi
__device__ __nv_bfloat16 g_blo[NOUT3 * KD];            // w_qkv lo
__device__ float g_qkv[(size_t)MPAD * NOUT3];          // qkv projections (fp32)
__device__ float g_o[(size_t)NB * OB_PER_B];           // attention out (scrambled-flat layout)
__device__ float g_ypre[NB * NWIN * NC];               // conv-reduced
__device__ float g_wpT[NC * NC];                       // w_proj transposed

// ======================= mma.sync helpers (baseline ISA, no tcgen05) =======================
__device__ __forceinline__ uint32_t smem_u32(const void* p) {
    uint32_t a;
    asm("{ .reg .u64 t; cvta.to.shared.u64 t, %1; cvt.u32.u64 %0, t; }" : "=r"(a) : "l"(p));
    return a;
}
__device__ __forceinline__ void ldsm_x4(uint32_t* r, uint32_t addr) {
    asm volatile("ldmatrix.sync.aligned.m8n8.x4.shared.b16 {%0,%1,%2,%3}, [%4];"
                 : "=r"(r[0]), "=r"(r[1]), "=r"(r[2]), "=r"(r[3]) : "r"(addr));
}
__device__ __forceinline__ void mma16816(float* c, const uint32_t* a, const uint32_t* b) {
    asm volatile("mma.sync.aligned.m16n8k16.row.col.f32.bf16.bf16.f32 "
                 "{%0,%1,%2,%3}, {%4,%5,%6,%7}, {%8,%9}, {%0,%1,%2,%3};"
                 : "+f"(c[0]), "+f"(c[1]), "+f"(c[2]), "+f"(c[3])
                 : "r"(a[0]), "r"(a[1]), "r"(a[2]), "r"(a[3]), "r"(b[0]), "r"(b[1]));
}

// -------- K0: x (B,C,H,W) -> xt (B,H,W,C) --------
__global__ void k_transpose_x(const float* __restrict__ x) {
    int idx = blockIdx.x * 256 + threadIdx.x;
    if (idx >= NB * NHW * NHW * NC) return;
    int c = idx & 255;
    int rem = idx >> 8;
    int pix = rem & 4095;
    int b = rem >> 12;
    g_xt[idx] = x[(((size_t)b * NC + c) << 12) + pix];
}

// -------- K1: poly eval + bilinear sample -> Ahi/Alo[b,n,s,c] (bf16 split) --------
__global__ void k_sample(const float* __restrict__ polys) {
    int j = blockIdx.x;                                // 0..58799 = ((b*600+n)*49+s)
    int t = threadIdx.x;                               // 0..63, 4 channels each
    int b = j / (NWIN * WS2);
    int r = j - b * (NWIN * WS2);
    int n = r / WS2;
    int s = r - n * WS2;
    int q = n / NP;
    int nid = n - q * NP;
    int m = nid * WS2 + s;
    int w = m / NP;
    int p = m - w * NP;

    const float* pc = polys + ((size_t)(b * NQ + q) * 2) * NP;
    float a = (float)p * 0.2f;
    float py = pc[0];
    #pragma unroll
    for (int i = 1; i < NP; i++) py = py * a + pc[i];
    float px = pc[NP];
    #pragma unroll
    for (int i = 1; i < NP; i++) px = px * a + pc[NP + i];
    py = 2.f * py - 1.f;
    px = 2.f * px - 1.f;

    int wy = w / WSZ, wx = w - wy * WSZ;
    float dy = (-4.0f + (float)wy * (7.0f / 6.0f)) * (2.0f / 64.0f);
    float dx = (-4.0f + (float)wx * (7.0f / 6.0f)) * (2.0f / 64.0f);
    float gy = py + dy, gx = px + dx;

    float fx = (gy + 1.f) * 0.5f * 63.f;
    float fy = (gx + 1.f) * 0.5f * 63.f;
    float x0f = floorf(fx), y0f = floorf(fy);
    float wx1 = fx - x0f, wy1 = fy - y0f;

    float vx0 = (x0f >= 0.f && x0f <= 63.f) ? 1.f : 0.f;
    float vx1 = (x0f + 1.f >= 0.f && x0f + 1.f <= 63.f) ? 1.f : 0.f;
    float vy0 = (y0f >= 0.f && y0f <= 63.f) ? 1.f : 0.f;
    float vy1 = (y0f + 1.f >= 0.f && y0f + 1.f <= 63.f) ? 1.f : 0.f;
    int xi0 = min(max((int)x0f, 0), 63);
    int xi1 = min(max((int)x0f + 1, 0), 63);
    int yi0 = min(max((int)y0f, 0), 63);
    int yi1 = min(max((int)y0f + 1, 0), 63);

    float w00 = (1.f - wy1) * (1.f - wx1) * vy0 * vx0;
    float w01 = (1.f - wy1) * wx1 * vy0 * vx1;
    float w10 = wy1 * (1.f - wx1) * vy1 * vx0;
    float w11 = wy1 * wx1 * vy1 * vx1;

    const float4* xt4 = (const float4*)g_xt;
    size_t pbase = (size_t)b * 4096;
    const float4* p00 = xt4 + (pbase + yi0 * 64 + xi0) * 64;
    const float4* p01 = xt4 + (pbase + yi0 * 64 + xi1) * 64;
    const float4* p10 = xt4 + (pbase + yi1 * 64 + xi0) * 64;
    const float4* p11 = xt4 + (pbase + yi1 * 64 + xi1) * 64;
    float4 v00 = p00[t], v01 = p01[t], v10 = p10[t], v11 = p11[t];
    float4 o;
    o.x = w00 * v00.x + w01 * v01.x + w10 * v10.x + w11 * v11.x;
    o.y = w00 * v00.y + w01 * v01.y + w10 * v10.y + w11 * v11.y;
    o.z = w00 * v00.z + w01 * v01.z + w10 * v10.z + w11 * v11.z;
    o.w = w00 * v00.w + w01 * v01.w + w10 * v10.w + w11 * v11.w;

    // two-term bf16 split
    __nv_bfloat16 h0 = __float2bfloat16(o.x), h1 = __float2bfloat16(o.y);
    __nv_bfloat16 h2 = __float2bfloat16(o.z), h3 = __float2bfloat16(o.w);
    __nv_bfloat16 l0 = __float2bfloat16(o.x - __bfloat162float(h0));
    __nv_bfloat16 l1 = __float2bfloat16(o.y - __bfloat162float(h1));
    __nv_bfloat16 l2 = __float2bfloat16(o.z - __bfloat162float(h2));
    __nv_bfloat16 l3 = __float2bfloat16(o.w - __bfloat162float(h3));
    __nv_bfloat162 hv0; hv0.x = h0; hv0.y = h1;
    __nv_bfloat162 hv1; hv1.x = h2; hv1.y = h3;
    __nv_bfloat162 lv0; lv0.x = l0; lv0.y = l1;
    __nv_bfloat162 lv1; lv1.x = l2; lv1.y = l3;
    size_t base2 = (size_t)j * 128 + t * 2;            // bf16x2 units
    ((__nv_bfloat162*)g_ahi)[base2] = hv0;
    ((__nv_bfloat162*)g_ahi)[base2 + 1] = hv1;
    ((__nv_bfloat162*)g_alo)[base2] = lv0;
    ((__nv_bfloat162*)g_alo)[base2 + 1] = lv1;
}

// -------- K1b: w_qkv -> bf16 hi/lo --------
__global__ void k_wconv(const float* __restrict__ wq) {
    int i = blockIdx.x * 256 + threadIdx.x;            // < 196608
    float v = wq[i];
    __nv_bfloat16 h = __float2bfloat16(v);
    g_bhi[i] = h;
    g_blo[i] = __float2bfloat16(v - __bfloat162float(h));
}

// -------- K2: HMMA GEMM: qkv = A @ B^T + bias (M=58880, K=256, N=768) --------
// CTA tile 128x128, 8 warps (4m x 2n), warp tile 32x64, K chunk 32.
// 3 bf16 terms: Ah*Bh + Ah*Bl + Al*Bh.
#define SROW 40   // smem row stride in bf16 (80B -> conflict-free ldmatrix)
__global__ void __launch_bounds__(256) k_gemm_mma(const float* __restrict__ bq) {
    __shared__ __align__(16) __nv_bfloat16 sAh[128][SROW];
    __shared__ __align__(16) __nv_bfloat16 sAl[128][SROW];
    __shared__ __align__(16) __nv_bfloat16 sBh[128][SROW];
    __shared__ __align__(16) __nv_bfloat16 sBl[128][SROW];

    int tid = threadIdx.x;
    int wid = tid >> 5, lid = tid & 31;
    int wm = wid >> 1, wn = wid & 1;                   // 4 x 2 warp grid
    int bm = blockIdx.x * 128, bn = blockIdx.y * 128;

    float acc[2][8][4];
    #pragma unroll
    for (int t = 0; t < 2; t++)
        #pragma unroll
        for (int j = 0; j < 8; j++)
            #pragma unroll
            for (int e = 0; e < 4; e++) acc[t][j][e] = 0.f;

    uint32_t uAh = smem_u32(&sAh[0][0]);
    uint32_t uAl = smem_u32(&sAl[0][0]);
    uint32_t uBh = smem_u32(&sBh[0][0]);
    uint32_t uBl = smem_u32(&sBl[0][0]);

    // ldmatrix lane addressing
    int arow = lid & 15;                               // A: rows 0-15, cols by hi bit
    int acolb = (lid >> 4) * 16;
    int brow = ((lid >> 4) & 1) * 8 + (lid & 7);       // B: n-rows, k-col by bit3
    int bcolb = ((lid >> 3) & 1) * 16;

    uint32_t aA0 = (uint32_t)((wm * 32 + arow) * (SROW * 2)) + acolb;
    uint32_t aB0 = (uint32_t)((wn * 64 + brow) * (SROW * 2)) + bcolb;

    const uint4* GAh = (const uint4*)g_ahi;
    const uint4* GAl = (const uint4*)g_alo;
    const uint4* GBh = (const uint4*)g_bhi;
    const uint4* GBl = (const uint4*)g_blo;

    for (int kc = 0; kc < 8; kc++) {
        #pragma unroll
        for (int i = tid; i < 512; i += 256) {
            int r = i >> 2, u = i & 3;
            size_t gai = (size_t)(bm + r) * 32 + kc * 4 + u;
            size_t gbi = (size_t)(bn + r) * 32 + kc * 4 + u;
            *(uint4*)((char*)&sAh[r][0] + u * 16) = GAh[gai];
            *(uint4*)((char*)&sAl[r][0] + u * 16) = GAl[gai];
            *(uint4*)((char*)&sBh[r][0] + u * 16) = GBh[gbi];
            *(uint4*)((char*)&sBl[r][0] + u * 16) = GBl[gbi];
        }
        __syncthreads();
        #pragma unroll
        for (int ks = 0; ks < 2; ks++) {
            uint32_t ah[2][4], al[2][4];
            ldsm_x4(ah[0], uAh + aA0 + ks * 32);
            ldsm_x4(ah[1], uAh + aA0 + 16 * (SROW * 2) + ks * 32);
            ldsm_x4(al[0], uAl + aA0 + ks * 32);
            ldsm_x4(al[1], uAl + aA0 + 16 * (SROW * 2) + ks * 32);
            #pragma unroll
            for (int j = 0; j < 4; j++) {
                uint32_t bh[4], bl[4];
                ldsm_x4(bh, uBh + aB0 + j * 16 * (SROW * 2) + ks * 32);
                ldsm_x4(bl, uBl + aB0 + j * 16 * (SROW * 2) + ks * 32);
                #pragma unroll
                for (int t = 0; t < 2; t++) {
                    mma16816(acc[t][j * 2],     ah[t], bh);
                    mma16816(acc[t][j * 2 + 1], ah[t], bh + 2);
                    mma16816(acc[t][j * 2],     ah[t], bl);
                    mma16816(acc[t][j * 2 + 1], ah[t], bl + 2);
                    mma16816(acc[t][j * 2],     al[t], bh);
                    mma16816(acc[t][j * 2 + 1], al[t], bh + 2);
                }
            }
        }
        __syncthreads();
    }

    // epilogue: c-frag -> float2 stores + bias
    int crow0 = bm + wm * 32 + (lid >> 2);
    int ccol0 = bn + wn * 64 + (lid & 3) * 2;
    #pragma unroll
    for (int t = 0; t < 2; t++) {
        #pragma unroll
        for (int j = 0; j < 8; j++) {
            int col = ccol0 + j * 8;
            float b0 = __ldg(&bq[col]);
            float b1 = __ldg(&bq[col + 1]);
            int row = crow0 + t * 16;
            float2 v0 = make_float2(acc[t][j][0] + b0, acc[t][j][1] + b1);
            float2 v1 = make_float2(acc[t][j][2] + b0, acc[t][j][3] + b1);
            *(float2*)&g_qkv[(size_t)row * NOUT3 + col] = v0;
            *(float2*)&g_qkv[(size_t)(row + 8) * NOUT3 + col] = v1;
        }
    }
}

// -------- K3: per-(b,h,n) windowed attention (register-tiled) --------
__global__ void __launch_bounds__(256) k_attn(const float* __restrict__ pos_bias) {
    int blk = blockIdx.x;                              // b*4800 + h*600 + n
    int b = blk / (NHD * NWIN);
    int r = blk - b * NHD * NWIN;
    int h = r / NWIN;
    int n = r - h * NWIN;

    __shared__ float qs[WS2][36];
    __shared__ float ks[WS2][36];
    __shared__ float vs[WS2][32];
    __shared__ float S[WS2][WS2];
    __shared__ float pbs[WS2];
    int tid = threadIdx.x;
    if (tid < WS2) pbs[tid] = pos_bias[tid];

    size_t rowbase = (size_t)(b * NWIN + n) * WS2 * NOUT3 + h * HDD;
    for (int e = tid; e < WS2 * HDD; e += 256) {
        int sidx = e >> 5, d = e & 31;
        size_t rb = rowbase + (size_t)sidx * NOUT3 + d;
        qs[sidx][d] = g_qkv[rb];
        ks[sidx][d] = g_qkv[rb + 256];
        vs[sidx][d] = g_qkv[rb + 512];
    }
    __syncthreads();

    const float scale = 0.17677669529663687f;          // 1/sqrt(32)
    int pp = tid >> 2, qtr = tid & 3;
    if (pp < WS2) {
        float4 q[8];
        const float4* q4 = (const float4*)qs[pp];
        #pragma unroll
        for (int i = 0; i < 8; i++) q[i] = q4[i];
        float pb = pbs[pp];
        int cc0 = qtr * 13;
        int ccn = (qtr < 3) ? 13 : 10;
        for (int c = cc0; c < cc0 + ccn; c++) {
            const float4* k4 = (const float4*)ks[c];
            float acc = 0.f;
            #pragma unroll
            for (int i = 0; i < 8; i++) {
                float4 kv = k4[i];
                acc += q[i].x * kv.x + q[i].y * kv.y + q[i].z * kv.z + q[i].w * kv.w;
            }
            S[pp][c] = acc * scale + pb;
        }
    }
    __syncthreads();

    if (tid < WS2) {
        float mx = -1e30f;
        #pragma unroll 7
        for (int c = 0; c < WS2; c++) mx = fmaxf(mx, S[tid][c]);
        float sum = 0.f;
        #pragma unroll 7
        for (int c = 0; c < WS2; c++) { float ev = __expf(S[tid][c] - mx); S[tid][c] = ev; sum += ev; }
        float inv = 1.f / sum;
        #pragma unroll 7
        for (int c = 0; c < WS2; c++) S[tid][c] *= inv;
    }
    __syncthreads();

    // o[b,h,n,p,d] at batch-flat offset h*940800 + p*19200 + n*32 + d
    size_t obase = (size_t)b * OB_PER_B + (size_t)h * (WS2 * NWIN * HDD) + (size_t)n * HDD;
    if (pp < WS2) {
        int d0 = qtr * 8;
        float acc[8] = {0.f, 0.f, 0.f, 0.f, 0.f, 0.f, 0.f, 0.f};
        #pragma unroll 7
        for (int c = 0; c < WS2; c++) {
            float sv = S[pp][c];
            float4 va = *(const float4*)&vs[c][d0];
            float4 vb = *(const float4*)&vs[c][d0 + 4];
            acc[0] += sv * va.x; acc[1] += sv * va.y; acc[2] += sv * va.z; acc[3] += sv * va.w;
            acc[4] += sv * vb.x; acc[5] += sv * vb.y; acc[6] += sv * vb.z; acc[7] += sv * vb.w;
        }
        float4 o0 = make_float4(acc[0], acc[1], acc[2], acc[3]);
        float4 o1 = make_float4(acc[4], acc[5], acc[6], acc[7]);
        size_t ob = obase + (size_t)pp * (NWIN * HDD) + d0;
        *(float4*)&g_o[ob] = o0;
        *(float4*)&g_o[ob + 4] = o1;
    }
}

// -------- K4: conv reduce over scrambled s2 axis --------
__global__ void k_conv(const float* __restrict__ conv_w, const float* __restrict__ conv_b) {
    __shared__ float cw[WS2];
    int tid = threadIdx.x;
    if (tid < WS2) cw[tid] = conv_w[tid];
    __syncthreads();
    int idx = blockIdx.x * 256 + tid;                  // < 307200
    int b = idx / (NWIN * NC);
    int r = idx - b * (NWIN * NC);
    int n2 = r >> 8, c2 = r & 255;
    size_t base = (size_t)b * OB_PER_B + (size_t)n2 * (WS2 * NC) + c2;
    float accv = conv_b[0];
    #pragma unroll 7
    for (int s2 = 0; s2 < WS2; s2++) accv += cw[s2] * g_o[base + (size_t)s2 * NC];
    g_ypre[idx] = accv;
}

// -------- K5a: transpose w_proj --------
__global__ void k_wpt(const float* __restrict__ wp) {
    int idx = blockIdx.x * 256 + threadIdx.x;          // < 65536
    int k = idx >> 8, c = idx & 255;
    g_wpT[idx] = wp[c * NC + k];
}

// -------- K5b: y = ypre @ w_proj^T + b_proj (4 rows/block) --------
__global__ void __launch_bounds__(256) k_proj(const float* __restrict__ bp, float* __restrict__ out) {
    __shared__ float rowv[4][NC];
    int row0 = blockIdx.x * 4;
    int c = threadIdx.x;
    #pragma unroll
    for (int i = 0; i < 4; i++) rowv[i][c] = g_ypre[(size_t)(row0 + i) * NC + c];
    __syncthreads();
    float a0 = 0.f, a1 = 0.f, a2 = 0.f, a3 = 0.f;
    #pragma unroll 8
    for (int k = 0; k < NC; k++) {
        float wv = g_wpT[k * NC + c];
        a0 += rowv[0][k] * wv; a1 += rowv[1][k] * wv;
        a2 += rowv[2][k] * wv; a3 += rowv[3][k] * wv;
    }
    float bb = bp[c];
    out[(size_t)(row0 + 0) * NC + c] = a0 + bb;
    out[(size_t)(row0 + 1) * NC + c] = a1 + bb;
    out[(size_t)(row0 + 2) * NC + c] = a2 + bb;
    out[(size_t)(row0 + 3) * NC + c] = a3 + bb;
}

extern "C" void kernel_launch(void* const* d_in, const int* in_sizes, int n_in,
                              void* d_out, int out_size) {
    const float* x        = (const float*)d_in[0];
    const float* polys    = (const float*)d_in[1];
    const float* w_qkv    = (const float*)d_in[2];
    const float* b_qkv    = (const float*)d_in[3];
    const float* w_proj   = (const float*)d_in[4];
    const float* b_proj   = (const float*)d_in[5];
    const float* conv_w   = (const float*)d_in[6];
    const float* conv_b   = (const float*)d_in[7];
    const float* pos_bias = (const float*)d_in[8];
    float* out = (float*)d_out;

    k_transpose_x<<<(NB * NHW * NHW * NC + 255) / 256, 256>>>(x);
    k_sample<<<NROWS, 64>>>(polys);
    k_wconv<<<(NOUT3 * KD) / 256, 256>>>(w_qkv);
    dim3 g2(MPAD / 128, NOUT3 / 128);
    k_gemm_mma<<<g2, 256>>>(b_qkv);
    k_attn<<<NB * NHD * NWIN, 256>>>(pos_bias);
    k_conv<<<(NB * NWIN * NC) / 256, 256>>>(conv_w, conv_b);
    k_wpt<<<NC * NC / 256, 256>>>(w_proj);
    k_proj<<<NB * NWIN / 4, 256>>>(b_proj, out);
}

// round 5
// speedup vs baseline: 1.5094x; 1.0304x over previous
#include <cuda_runtime.h>
#include <cuda_bf16.h>
#include <cstdint>
#include <math.h>

#define NB 2
#define NQ 100
#define NC 256
#define NHW 64
#define NP 6
#define WSZ 7
#define WS2 49
#define NHD 8
#define HDD 32
#define NWIN 600            // Q*NP
#define NROWS 58800         // NB*NWIN*WS2
#define MPAD 58880          // 460*128 (GEMM M padding)
#define KD 256
#define NOUT3 768
#define OB_PER_B 7526400    // NHD*WS2*NWIN*HDD

// -------- scratch (static device globals; no runtime alloc allowed) --------
__device__ float g_xt[NB * NHW * NHW * NC];            // x transposed to (b,y,x,c)
__device__ __nv_bfloat16 g_ahi[(size_t)MPAD * KD];     // sampled features hi (bf16)
__device__ __nv_bfloat16 g_alo[(size_t)MPAD * KD];     // sampled features lo (bf16)
__device__ __nv_bfloat16 g_bhi[NOUT3 * KD];            // w_qkv hi
__device__ __nv_bfloat16 g_blo[NOUT3 * KD];            // w_qkv lo
__device__ float g_qkv[(size_t)MPAD * NOUT3];          // qkv projections (fp32)
__device__ float g_o[(size_t)NB * OB_PER_B];           // attention out (scrambled-flat layout)
__device__ float g_ypre[NB * NWIN * NC];               // conv-reduced
__device__ float g_wpT[NC * NC];                       // w_proj transposed

// ======================= mma.sync / cp.async helpers (baseline ISA) =======================
__device__ __forceinline__ uint32_t smem_u32(const void* p) {
    uint32_t a;
    asm("{ .reg .u64 t; cvta.to.shared.u64 t, %1; cvt.u32.u64 %0, t; }" : "=r"(a) : "l"(p));
    return a;
}
__device__ __forceinline__ void ldsm_x4(uint32_t* r, uint32_t addr) {
    asm volatile("ldmatrix.sync.aligned.m8n8.x4.shared.b16 {%0,%1,%2,%3}, [%4];"
                 : "=r"(r[0]), "=r"(r[1]), "=r"(r[2]), "=r"(r[3]) : "r"(addr));
}
__device__ __forceinline__ void mma16816(float* c, const uint32_t* a, const uint32_t* b) {
    asm volatile("mma.sync.aligned.m16n8k16.row.col.f32.bf16.bf16.f32 "
                 "{%0,%1,%2,%3}, {%4,%5,%6,%7}, {%8,%9}, {%0,%1,%2,%3};"
                 : "+f"(c[0]), "+f"(c[1]), "+f"(c[2]), "+f"(c[3])
                 : "r"(a[0]), "r"(a[1]), "r"(a[2]), "r"(a[3]), "r"(b[0]), "r"(b[1]));
}
__device__ __forceinline__ void cp_async16(uint32_t saddr, const void* gptr) {
    asm volatile("cp.async.cg.shared.global [%0], [%1], 16;" :: "r"(saddr), "l"(gptr));
}
#define CP_COMMIT() asm volatile("cp.async.commit_group;" ::: "memory")
#define CP_WAIT1() asm volatile("cp.async.wait_group 1;" ::: "memory")
#define CP_WAIT0() asm volatile("cp.async.wait_group 0;" ::: "memory")

// -------- K0: x (B,C,H,W) -> xt (B,H,W,C), tiled transpose --------
__global__ void k_transpose_x(const float* __restrict__ x) {
    __shared__ float tile[32][33];
    int b = blockIdx.z;
    int c0 = blockIdx.y * 32, p0 = blockIdx.x * 32;
    #pragma unroll
    for (int i = threadIdx.y; i < 32; i += 8)
        tile[i][threadIdx.x] = x[((size_t)(b * NC + c0 + i) << 12) + p0 + threadIdx.x];
    __syncthreads();
    #pragma unroll
    for (int i = threadIdx.y; i < 32; i += 8)
        g_xt[(((size_t)b << 12) + p0 + i) * NC + c0 + threadIdx.x] = tile[threadIdx.x][i];
}

// -------- K1: poly eval + bilinear sample -> Ahi/Alo[b,n,s,c] (bf16 split) --------
__global__ void k_sample(const float* __restrict__ polys) {
    int j = blockIdx.x;                                // 0..58799 = ((b*600+n)*49+s)
    int t = threadIdx.x;                               // 0..63, 4 channels each
    int b = j / (NWIN * WS2);
    int r = j - b * (NWIN * WS2);
    int n = r / WS2;
    int s = r - n * WS2;
    int q = n / NP;
    int nid = n - q * NP;
    int m = nid * WS2 + s;
    int w = m / NP;
    int p = m - w * NP;

    const float* pc = polys + ((size_t)(b * NQ + q) * 2) * NP;
    float a = (float)p * 0.2f;
    float py = pc[0];
    #pragma unroll
    for (int i = 1; i < NP; i++) py = py * a + pc[i];
    float px = pc[NP];
    #pragma unroll
    for (int i = 1; i < NP; i++) px = px * a + pc[NP + i];
    py = 2.f * py - 1.f;
    px = 2.f * px - 1.f;

    int wy = w / WSZ, wx = w - wy * WSZ;
    float dy = (-4.0f + (float)wy * (7.0f / 6.0f)) * (2.0f / 64.0f);
    float dx = (-4.0f + (float)wx * (7.0f / 6.0f)) * (2.0f / 64.0f);
    float gy = py + dy, gx = px + dx;

    float fx = (gy + 1.f) * 0.5f * 63.f;
    float fy = (gx + 1.f) * 0.5f * 63.f;
    float x0f = floorf(fx), y0f = floorf(fy);
    float wx1 = fx - x0f, wy1 = fy - y0f;

    float vx0 = (x0f >= 0.f && x0f <= 63.f) ? 1.f : 0.f;
    float vx1 = (x0f + 1.f >= 0.f && x0f + 1.f <= 63.f) ? 1.f : 0.f;
    float vy0 = (y0f >= 0.f && y0f <= 63.f) ? 1.f : 0.f;
    float vy1 = (y0f + 1.f >= 0.f && y0f + 1.f <= 63.f) ? 1.f : 0.f;
    int xi0 = min(max((int)x0f, 0), 63);
    int xi1 = min(max((int)x0f + 1, 0), 63);
    int yi0 = min(max((int)y0f, 0), 63);
    int yi1 = min(max((int)y0f + 1, 0), 63);

    float w00 = (1.f - wy1) * (1.f - wx1) * vy0 * vx0;
    float w01 = (1.f - wy1) * wx1 * vy0 * vx1;
    float w10 = wy1 * (1.f - wx1) * vy1 * vx0;
    float w11 = wy1 * wx1 * vy1 * vx1;

    const float4* xt4 = (const float4*)g_xt;
    size_t pbase = (size_t)b * 4096;
    const float4* p00 = xt4 + (pbase + yi0 * 64 + xi0) * 64;
    const float4* p01 = xt4 + (pbase + yi0 * 64 + xi1) * 64;
    const float4* p10 = xt4 + (pbase + yi1 * 64 + xi0) * 64;
    const float4* p11 = xt4 + (pbase + yi1 * 64 + xi1) * 64;
    float4 v00 = p00[t], v01 = p01[t], v10 = p10[t], v11 = p11[t];
    float4 o;
    o.x = w00 * v00.x + w01 * v01.x + w10 * v10.x + w11 * v11.x;
    o.y = w00 * v00.y + w01 * v01.y + w10 * v10.y + w11 * v11.y;
    o.z = w00 * v00.z + w01 * v01.z + w10 * v10.z + w11 * v11.z;
    o.w = w00 * v00.w + w01 * v01.w + w10 * v10.w + w11 * v11.w;

    // two-term bf16 split
    __nv_bfloat16 h0 = __float2bfloat16(o.x), h1 = __float2bfloat16(o.y);
    __nv_bfloat16 h2 = __float2bfloat16(o.z), h3 = __float2bfloat16(o.w);
    __nv_bfloat16 l0 = __float2bfloat16(o.x - __bfloat162float(h0));
    __nv_bfloat16 l1 = __float2bfloat16(o.y - __bfloat162float(h1));
    __nv_bfloat16 l2 = __float2bfloat16(o.z - __bfloat162float(h2));
    __nv_bfloat16 l3 = __float2bfloat16(o.w - __bfloat162float(h3));
    __nv_bfloat162 hv0; hv0.x = h0; hv0.y = h1;
    __nv_bfloat162 hv1; hv1.x = h2; hv1.y = h3;
    __nv_bfloat162 lv0; lv0.x = l0; lv0.y = l1;
    __nv_bfloat162 lv1; lv1.x = l2; lv1.y = l3;
    size_t base2 = (size_t)j * 128 + t * 2;            // bf16x2 units
    ((__nv_bfloat162*)g_ahi)[base2] = hv0;
    ((__nv_bfloat162*)g_ahi)[base2 + 1] = hv1;
    ((__nv_bfloat162*)g_alo)[base2] = lv0;
    ((__nv_bfloat162*)g_alo)[base2 + 1] = lv1;
}

// -------- K1b: w_qkv -> bf16 hi/lo --------
__global__ void k_wconv(const float* __restrict__ wq) {
    int i = blockIdx.x * 256 + threadIdx.x;            // < 196608
    float v = wq[i];
    __nv_bfloat16 h = __float2bfloat16(v);
    g_bhi[i] = h;
    g_blo[i] = __float2bfloat16(v - __bfloat162float(h));
}

// -------- K2: HMMA GEMM, cp.async double-buffered --------
// CTA tile 128x128, 8 warps (4m x 2n), warp tile 32x64, K chunk 32 (8 iters).
// 3 bf16 terms: Ah*Bh + Ah*Bl + Al*Bh.
#define SROW 40                     // smem row stride in bf16 (80B)
#define ARR_B (128 * SROW * 2)      // 10240 B per array
#define STAGE_B (4 * ARR_B)         // 40960 B per stage
#define GSM_TOTAL (2 * STAGE_B)     // 81920 B

__global__ void __launch_bounds__(256) k_gemm_mma(const float* __restrict__ bq) {
    extern __shared__ __align__(16) char dsm[];
    int tid = threadIdx.x;
    int wid = tid >> 5, lid = tid & 31;
    int wm = wid >> 1, wn = wid & 1;                   // 4 x 2 warp grid
    int bm = blockIdx.x * 128, bn = blockIdx.y * 128;

    float acc[2][8][4];
    #pragma unroll
    for (int t = 0; t < 2; t++)
        #pragma unroll
        for (int j = 0; j < 8; j++)
            #pragma unroll
            for (int e = 0; e < 4; e++) acc[t][j][e] = 0.f;

    uint32_t sbase = smem_u32(dsm);

    // cp.async source/dest indexing: 512 16B-chunks per array per stage
    int ldr = tid >> 1;                                // 0..127 row
    int ldu2 = (tid & 1) * 2;                          // chunk pair 0 or 2

    const char* GAh = (const char*)g_ahi;
    const char* GAl = (const char*)g_alo;
    const char* GBh = (const char*)g_bhi;
    const char* GBl = (const char*)g_blo;

    // ldmatrix lane addressing (within a stage)
    int arow = lid & 15;
    int acolb = (lid >> 4) * 16;
    int brow = ((lid >> 4) & 1) * 8 + (lid & 7);
    int bcolb = ((lid >> 3) & 1) * 16;
    uint32_t aA0 = (uint32_t)((wm * 32 + arow) * (SROW * 2)) + acolb;
    uint32_t aB0 = (uint32_t)((wn * 64 + brow) * (SROW * 2)) + bcolb;

    // stage loader: rows*4 chunks of 16B per array; each thread does 2 chunks x 4 arrays
    auto load_stage = [&](int kc, int st) {
        uint32_t sb = sbase + st * STAGE_B;
        size_t ga = ((size_t)(bm + ldr) * 32 + kc * 4 + ldu2) * 16;   // bytes into A arrays
        size_t gb = ((size_t)(bn + ldr) * 32 + kc * 4 + ldu2) * 16;
        uint32_t so = (uint32_t)(ldr * (SROW * 2)) + ldu2 * 16;
        #pragma unroll
        for (int u = 0; u < 2; u++) {
            cp_async16(sb + so + u * 16,               GAh + ga + u * 16);
            cp_async16(sb + ARR_B + so + u * 16,       GAl + ga + u * 16);
            cp_async16(sb + 2 * ARR_B + so + u * 16,   GBh + gb + u * 16);
            cp_async16(sb + 3 * ARR_B + so + u * 16,   GBl + gb + u * 16);
        }
    };

    load_stage(0, 0);
    CP_COMMIT();

    for (int kc = 0; kc < 8; kc++) {
        int st = kc & 1;
        if (kc < 7) {
            load_stage(kc + 1, st ^ 1);
            CP_COMMIT();
            CP_WAIT1();
        } else {
            CP_WAIT0();
        }
        __syncthreads();

        uint32_t uAh = sbase + st * STAGE_B;
        uint32_t uAl = uAh + ARR_B;
        uint32_t uBh = uAh + 2 * ARR_B;
        uint32_t uBl = uAh + 3 * ARR_B;
        #pragma unroll
        for (int ks = 0; ks < 2; ks++) {
            uint32_t ah[2][4], al[2][4];
            ldsm_x4(ah[0], uAh + aA0 + ks * 32);
            ldsm_x4(ah[1], uAh + aA0 + 16 * (SROW * 2) + ks * 32);
            ldsm_x4(al[0], uAl + aA0 + ks * 32);
            ldsm_x4(al[1], uAl + aA0 + 16 * (SROW * 2) + ks * 32);
            #pragma unroll
            for (int j = 0; j < 4; j++) {
                uint32_t bh[4], bl[4];
                ldsm_x4(bh, uBh + aB0 + j * 16 * (SROW * 2) + ks * 32);
                ldsm_x4(bl, uBl + aB0 + j * 16 * (SROW * 2) + ks * 32);
                #pragma unroll
                for (int t = 0; t < 2; t++) {
                    mma16816(acc[t][j * 2],     ah[t], bh);
                    mma16816(acc[t][j * 2 + 1], ah[t], bh + 2);
                    mma16816(acc[t][j * 2],     ah[t], bl);
                    mma16816(acc[t][j * 2 + 1], ah[t], bl + 2);
                    mma16816(acc[t][j * 2],     al[t], bh);
                    mma16816(acc[t][j * 2 + 1], al[t], bh + 2);
                }
            }
        }
        __syncthreads();
    }

    // epilogue: c-frag -> float2 stores + bias
    int crow0 = bm + wm * 32 + (lid >> 2);
    int ccol0 = bn + wn * 64 + (lid & 3) * 2;
    #pragma unroll
    for (int t = 0; t < 2; t++) {
        #pragma unroll
        for (int j = 0; j < 8; j++) {
            int col = ccol0 + j * 8;
            float b0 = __ldg(&bq[col]);
            float b1 = __ldg(&bq[col + 1]);
            int row = crow0 + t * 16;
            float2 v0 = make_float2(acc[t][j][0] + b0, acc[t][j][1] + b1);
            float2 v1 = make_float2(acc[t][j][2] + b0, acc[t][j][3] + b1);
            *(float2*)&g_qkv[(size_t)row * NOUT3 + col] = v0;
            *(float2*)&g_qkv[(size_t)(row + 8) * NOUT3 + col] = v1;
        }
    }
}

// -------- K3: per-(b,h,n) windowed attention (register-tiled) --------
__global__ void __launch_bounds__(256) k_attn(const float* __restrict__ pos_bias) {
    int blk = blockIdx.x;                              // b*4800 + h*600 + n
    int b = blk / (NHD * NWIN);
    int r = blk - b * NHD * NWIN;
    int h = r / NWIN;
    int n = r - h * NWIN;

    __shared__ float qs[WS2][36];
    __shared__ float ks[WS2][36];
    __shared__ float vs[WS2][32];
    __shared__ float S[WS2][WS2];
    __shared__ float pbs[WS2];
    int tid = threadIdx.x;
    if (tid < WS2) pbs[tid] = pos_bias[tid];

    size_t rowbase = (size_t)(b * NWIN + n) * WS2 * NOUT3 + h * HDD;
    for (int e = tid; e < WS2 * HDD; e += 256) {
        int sidx = e >> 5, d = e & 31;
        size_t rb = rowbase + (size_t)sidx * NOUT3 + d;
        qs[sidx][d] = g_qkv[rb];
        ks[sidx][d] = g_qkv[rb + 256];
        vs[sidx][d] = g_qkv[rb + 512];
    }
    __syncthreads();

    const float scale = 0.17677669529663687f;          // 1/sqrt(32)
    int pp = tid >> 2, qtr = tid & 3;
    if (pp < WS2) {
        float4 q[8];
        const float4* q4 = (const float4*)qs[pp];
        #pragma unroll
        for (int i = 0; i < 8; i++) q[i] = q4[i];
        float pb = pbs[pp];
        int cc0 = qtr * 13;
        int ccn = (qtr < 3) ? 13 : 10;
        for (int c = cc0; c < cc0 + ccn; c++) {
            const float4* k4 = (const float4*)ks[c];
            float acc = 0.f;
            #pragma unroll
            for (int i = 0; i < 8; i++) {
                float4 kv = k4[i];
                acc += q[i].x * kv.x + q[i].y * kv.y + q[i].z * kv.z + q[i].w * kv.w;
            }
            S[pp][c] = acc * scale + pb;
        }
    }
    __syncthreads();

    if (tid < WS2) {
        float mx = -1e30f;
        #pragma unroll 7
        for (int c = 0; c < WS2; c++) mx = fmaxf(mx, S[tid][c]);
        float sum = 0.f;
        #pragma unroll 7
        for (int c = 0; c < WS2; c++) { float ev = __expf(S[tid][c] - mx); S[tid][c] = ev; sum += ev; }
        float inv = 1.f / sum;
        #pragma unroll 7
        for (int c = 0; c < WS2; c++) S[tid][c] *= inv;
    }
    __syncthreads();

    // o[b,h,n,p,d] at batch-flat offset h*940800 + p*19200 + n*32 + d
    size_t obase = (size_t)b * OB_PER_B + (size_t)h * (WS2 * NWIN * HDD) + (size_t)n * HDD;
    if (pp < WS2) {
        int d0 = qtr * 8;
        float acc[8] = {0.f, 0.f, 0.f, 0.f, 0.f, 0.f, 0.f, 0.f};
        #pragma unroll 7
        for (int c = 0; c < WS2; c++) {
            float sv = S[pp][c];
            float4 va = *(const float4*)&vs[c][d0];
            float4 vb = *(const float4*)&vs[c][d0 + 4];
            acc[0] += sv * va.x; acc[1] += sv * va.y; acc[2] += sv * va.z; acc[3] += sv * va.w;
            acc[4] += sv * vb.x; acc[5] += sv * vb.y; acc[6] += sv * vb.z; acc[7] += sv * vb.w;
        }
        float4 o0 = make_float4(acc[0], acc[1], acc[2], acc[3]);
        float4 o1 = make_float4(acc[4], acc[5], acc[6], acc[7]);
        size_t ob = obase + (size_t)pp * (NWIN * HDD) + d0;
        *(float4*)&g_o[ob] = o0;
        *(float4*)&g_o[ob + 4] = o1;
    }
}

// -------- K4: conv reduce over scrambled s2 axis --------
__global__ void k_conv(const float* __restrict__ conv_w, const float* __restrict__ conv_b) {
    __shared__ float cw[WS2];
    int tid = threadIdx.x;
    if (tid < WS2) cw[tid] = conv_w[tid];
    __syncthreads();
    int idx = blockIdx.x * 256 + tid;                  // < 307200
    int b = idx / (NWIN * NC);
    int r = idx - b * (NWIN * NC);
    int n2 = r >> 8, c2 = r & 255;
    size_t base = (size_t)b * OB_PER_B + (size_t)n2 * (WS2 * NC) + c2;
    float accv = conv_b[0];
    #pragma unroll 7
    for (int s2 = 0; s2 < WS2; s2++) accv += cw[s2] * g_o[base + (size_t)s2 * NC];
    g_ypre[idx] = accv;
}

// -------- K5a: transpose w_proj --------
__global__ void k_wpt(const float* __restrict__ wp) {
    int idx = blockIdx.x * 256 + threadIdx.x;          // < 65536
    int k = idx >> 8, c = idx & 255;
    g_wpT[idx] = wp[c * NC + k];
}

// -------- K5b: y = ypre @ w_proj^T + b_proj (4 rows/block) --------
__global__ void __launch_bounds__(256) k_proj(const float* __restrict__ bp, float* __restrict__ out) {
    __shared__ float rowv[4][NC];
    int row0 = blockIdx.x * 4;
    int c = threadIdx.x;
    #pragma unroll
    for (int i = 0; i < 4; i++) rowv[i][c] = g_ypre[(size_t)(row0 + i) * NC + c];
    __syncthreads();
    float a0 = 0.f, a1 = 0.f, a2 = 0.f, a3 = 0.f;
    #pragma unroll 8
    for (int k = 0; k < NC; k++) {
        float wv = g_wpT[k * NC + c];
        a0 += rowv[0][k] * wv; a1 += rowv[1][k] * wv;
        a2 += rowv[2][k] * wv; a3 += rowv[3][k] * wv;
    }
    float bb = bp[c];
    out[(size_t)(row0 + 0) * NC + c] = a0 + bb;
    out[(size_t)(row0 + 1) * NC + c] = a1 + bb;
    out[(size_t)(row0 + 2) * NC + c] = a2 + bb;
    out[(size_t)(row0 + 3) * NC + c] = a3 + bb;
}

extern "C" void kernel_launch(void* const* d_in, const int* in_sizes, int n_in,
                              void* d_out, int out_size) {
    const float* x        = (const float*)d_in[0];
    const float* polys    = (const float*)d_in[1];
    const float* w_qkv    = (const float*)d_in[2];
    const float* b_qkv    = (const float*)d_in[3];
    const float* w_proj   = (const float*)d_in[4];
    const float* b_proj   = (const float*)d_in[5];
    const float* conv_w   = (const float*)d_in[6];
    const float* conv_b   = (const float*)d_in[7];
    const float* pos_bias = (const float*)d_in[8];
    float* out = (float*)d_out;

    static int smem_set = 0;
    if (!smem_set) {
        cudaFuncSetAttribute(k_gemm_mma, cudaFuncAttributeMaxDynamicSharedMemorySize, GSM_TOTAL);
        smem_set = 1;
    }

    dim3 gt(128, 8, 2);
    dim3 bt(32, 8);
    k_transpose_x<<<gt, bt>>>(x);
    k_sample<<<NROWS, 64>>>(polys);
    k_wconv<<<(NOUT3 * KD) / 256, 256>>>(w_qkv);
    dim3 g2(MPAD / 128, NOUT3 / 128);
    k_gemm_mma<<<g2, 256, GSM_TOTAL>>>(b_qkv);
    k_attn<<<NB * NHD * NWIN, 256>>>(pos_bias);
    k_conv<<<(NB * NWIN * NC) / 256, 256>>>(conv_w, conv_b);
    k_wpt<<<NC * NC / 256, 256>>>(w_proj);
    k_proj<<<NB * NWIN / 4, 256>>>(b_proj, out);
}

// round 7
// speedup vs baseline: 1.6776x; 1.1115x over previous
#include <cuda_runtime.h>
#include <cuda_bf16.h>
#include <cstdint>
#include <math.h>

#define NB 2
#define NQ 100
#define NC 256
#define NHW 64
#define NP 6
#define WSZ 7
#define WS2 49
#define NHD 8
#define HDD 32
#define NWIN 600            // Q*NP
#define NROWS 58800         // NB*NWIN*WS2
#define MPAD 58880          // 460*128 (GEMM M padding)
#define KD 256
#define NOUT3 768
#define OB_PER_B 7526400    // NHD*WS2*NWIN*HDD

// -------- scratch (static device globals; no runtime alloc allowed) --------
__device__ float g_xt[NB * NHW * NHW * NC];            // x transposed to (b,y,x,c)
__device__ __nv_bfloat16 g_ahi[(size_t)MPAD * KD];     // sampled features hi (bf16)
__device__ __nv_bfloat16 g_alo[(size_t)MPAD * KD];     // sampled features lo (bf16)
__device__ __nv_bfloat16 g_bhi[NOUT3 * KD];            // w_qkv hi
__device__ __nv_bfloat16 g_blo[NOUT3 * KD];            // w_qkv lo
__device__ float g_qkv[(size_t)MPAD * NOUT3];          // qkv projections (fp32)
__device__ float g_o[(size_t)NB * OB_PER_B];           // attention out (scrambled-flat layout)
__device__ float g_ypre[NB * NWIN * NC];               // conv-reduced
__device__ float g_wpT[NC * NC];                       // w_proj transposed

// ======================= mma.sync / cp.async helpers (baseline ISA) =======================
__device__ __forceinline__ uint32_t smem_u32(const void* p) {
    uint32_t a;
    asm("{ .reg .u64 t; cvta.to.shared.u64 t, %1; cvt.u32.u64 %0, t; }" : "=r"(a) : "l"(p));
    return a;
}
__device__ __forceinline__ void ldsm_x4(uint32_t* r, uint32_t addr) {
    asm volatile("ldmatrix.sync.aligned.m8n8.x4.shared.b16 {%0,%1,%2,%3}, [%4];"
                 : "=r"(r[0]), "=r"(r[1]), "=r"(r[2]), "=r"(r[3]) : "r"(addr));
}
__device__ __forceinline__ void mma16816(float* c, const uint32_t* a, const uint32_t* b) {
    asm volatile("mma.sync.aligned.m16n8k16.row.col.f32.bf16.bf16.f32 "
                 "{%0,%1,%2,%3}, {%4,%5,%6,%7}, {%8,%9}, {%0,%1,%2,%3};"
                 : "+f"(c[0]), "+f"(c[1]), "+f"(c[2]), "+f"(c[3])
                 : "r"(a[0]), "r"(a[1]), "r"(a[2]), "r"(a[3]), "r"(b[0]), "r"(b[1]));
}
__device__ __forceinline__ void cp_async16(uint32_t saddr, const void* gptr) {
    asm volatile("cp.async.cg.shared.global [%0], [%1], 16;" :: "r"(saddr), "l"(gptr));
}
#define CP_COMMIT() asm volatile("cp.async.commit_group;" ::: "memory")
#define CP_WAIT1() asm volatile("cp.async.wait_group 1;" ::: "memory")
#define CP_WAIT0() asm volatile("cp.async.wait_group 0;" ::: "memory")

// -------- K0: x (B,C,H,W) -> xt (B,H,W,C), tiled transpose --------
__global__ void k_transpose_x(const float* __restrict__ x) {
    __shared__ float tile[32][33];
    int b = blockIdx.z;
    int c0 = blockIdx.y * 32, p0 = blockIdx.x * 32;
    #pragma unroll
    for (int i = threadIdx.y; i < 32; i += 8)
        tile[i][threadIdx.x] = x[((size_t)(b * NC + c0 + i) << 12) + p0 + threadIdx.x];
    __syncthreads();
    #pragma unroll
    for (int i = threadIdx.y; i < 32; i += 8)
        g_xt[(((size_t)b << 12) + p0 + i) * NC + c0 + threadIdx.x] = tile[threadIdx.x][i];
}

// -------- K1: poly eval + bilinear sample -> Ahi/Alo[b,n,s,c] (bf16 split) --------
__global__ void k_sample(const float* __restrict__ polys) {
    int j = blockIdx.x;                                // 0..58799 = ((b*600+n)*49+s)
    int t = threadIdx.x;                               // 0..63, 4 channels each
    int b = j / (NWIN * WS2);
    int r = j - b * (NWIN * WS2);
    int n = r / WS2;
    int s = r - n * WS2;
    int q = n / NP;
    int nid = n - q * NP;
    int m = nid * WS2 + s;
    int w = m / NP;
    int p = m - w * NP;

    const float* pc = polys + ((size_t)(b * NQ + q) * 2) * NP;
    float a = (float)p * 0.2f;
    float py = pc[0];
    #pragma unroll
    for (int i = 1; i < NP; i++) py = py * a + pc[i];
    float px = pc[NP];
    #pragma unroll
    for (int i = 1; i < NP; i++) px = px * a + pc[NP + i];
    py = 2.f * py - 1.f;
    px = 2.f * px - 1.f;

    int wy = w / WSZ, wx = w - wy * WSZ;
    float dy = (-4.0f + (float)wy * (7.0f / 6.0f)) * (2.0f / 64.0f);
    float dx = (-4.0f + (float)wx * (7.0f / 6.0f)) * (2.0f / 64.0f);
    float gy = py + dy, gx = px + dx;

    float fx = (gy + 1.f) * 0.5f * 63.f;
    float fy = (gx + 1.f) * 0.5f * 63.f;
    float x0f = floorf(fx), y0f = floorf(fy);
    float wx1 = fx - x0f, wy1 = fy - y0f;

    float vx0 = (x0f >= 0.f && x0f <= 63.f) ? 1.f : 0.f;
    float vx1 = (x0f + 1.f >= 0.f && x0f + 1.f <= 63.f) ? 1.f : 0.f;
    float vy0 = (y0f >= 0.f && y0f <= 63.f) ? 1.f : 0.f;
    float vy1 = (y0f + 1.f >= 0.f && y0f + 1.f <= 63.f) ? 1.f : 0.f;
    int xi0 = min(max((int)x0f, 0), 63);
    int xi1 = min(max((int)x0f + 1, 0), 63);
    int yi0 = min(max((int)y0f, 0), 63);
    int yi1 = min(max((int)y0f + 1, 0), 63);

    float w00 = (1.f - wy1) * (1.f - wx1) * vy0 * vx0;
    float w01 = (1.f - wy1) * wx1 * vy0 * vx1;
    float w10 = wy1 * (1.f - wx1) * vy1 * vx0;
    float w11 = wy1 * wx1 * vy1 * vx1;

    const float4* xt4 = (const float4*)g_xt;
    size_t pbase = (size_t)b * 4096;
    const float4* p00 = xt4 + (pbase + yi0 * 64 + xi0) * 64;
    const float4* p01 = xt4 + (pbase + yi0 * 64 + xi1) * 64;
    const float4* p10 = xt4 + (pbase + yi1 * 64 + xi0) * 64;
    const float4* p11 = xt4 + (pbase + yi1 * 64 + xi1) * 64;
    float4 v00 = p00[t], v01 = p01[t], v10 = p10[t], v11 = p11[t];
    float4 o;
    o.x = w00 * v00.x + w01 * v01.x + w10 * v10.x + w11 * v11.x;
    o.y = w00 * v00.y + w01 * v01.y + w10 * v10.y + w11 * v11.y;
    o.z = w00 * v00.z + w01 * v01.z + w10 * v10.z + w11 * v11.z;
    o.w = w00 * v00.w + w01 * v01.w + w10 * v10.w + w11 * v11.w;

    // two-term bf16 split
    __nv_bfloat16 h0 = __float2bfloat16(o.x), h1 = __float2bfloat16(o.y);
    __nv_bfloat16 h2 = __float2bfloat16(o.z), h3 = __float2bfloat16(o.w);
    __nv_bfloat16 l0 = __float2bfloat16(o.x - __bfloat162float(h0));
    __nv_bfloat16 l1 = __float2bfloat16(o.y - __bfloat162float(h1));
    __nv_bfloat16 l2 = __float2bfloat16(o.z - __bfloat162float(h2));
    __nv_bfloat16 l3 = __float2bfloat16(o.w - __bfloat162float(h3));
    __nv_bfloat162 hv0; hv0.x = h0; hv0.y = h1;
    __nv_bfloat162 hv1; hv1.x = h2; hv1.y = h3;
    __nv_bfloat162 lv0; lv0.x = l0; lv0.y = l1;
    __nv_bfloat162 lv1; lv1.x = l2; lv1.y = l3;
    size_t base2 = (size_t)j * 128 + t * 2;            // bf16x2 units
    ((__nv_bfloat162*)g_ahi)[base2] = hv0;
    ((__nv_bfloat162*)g_ahi)[base2 + 1] = hv1;
    ((__nv_bfloat162*)g_alo)[base2] = lv0;
    ((__nv_bfloat162*)g_alo)[base2 + 1] = lv1;
}

// -------- K1b: w_qkv -> bf16 hi/lo --------
__global__ void k_wconv(const float* __restrict__ wq) {
    int i = blockIdx.x * 256 + threadIdx.x;            // < 196608
    float v = wq[i];
    __nv_bfloat16 h = __float2bfloat16(v);
    g_bhi[i] = h;
    g_blo[i] = __float2bfloat16(v - __bfloat162float(h));
}

// -------- K2: HMMA GEMM, cp.async double-buffered, 2 CTAs/SM --------
// CTA tile 128x128, 8 warps (4m x 2n), warp tile 32x64, K chunk 32 (8 iters).
// 3 bf16 terms: Ah*Bh + Ah*Bl + Al*Bh. MMA order gives dep spacing 4.
#define SROW 40                     // smem row stride in bf16 (80B)
#define ARR_B (128 * SROW * 2)      // 10240 B per array
#define STAGE_B (4 * ARR_B)         // 40960 B per stage
#define GSM_TOTAL (2 * STAGE_B)     // 81920 B

__global__ void __launch_bounds__(256, 2) k_gemm_mma(const float* __restrict__ bq) {
    extern __shared__ __align__(16) char dsm[];
    int tid = threadIdx.x;
    int wid = tid >> 5, lid = tid & 31;
    int wm = wid >> 1, wn = wid & 1;                   // 4 x 2 warp grid
    int bm = blockIdx.x * 128, bn = blockIdx.y * 128;

    float acc[2][8][4];
    #pragma unroll
    for (int t = 0; t < 2; t++)
        #pragma unroll
        for (int j = 0; j < 8; j++)
            #pragma unroll
            for (int e = 0; e < 4; e++) acc[t][j][e] = 0.f;

    uint32_t sbase = smem_u32(dsm);

    int ldr = tid >> 1;                                // 0..127 row
    int ldu2 = (tid & 1) * 2;                          // chunk pair 0 or 2

    const char* GAh = (const char*)g_ahi;
    const char* GAl = (const char*)g_alo;
    const char* GBh = (const char*)g_bhi;
    const char* GBl = (const char*)g_blo;

    int arow = lid & 15;
    int acolb = (lid >> 4) * 16;
    int brow = ((lid >> 4) & 1) * 8 + (lid & 7);
    int bcolb = ((lid >> 3) & 1) * 16;
    uint32_t aA0 = (uint32_t)((wm * 32 + arow) * (SROW * 2)) + acolb;
    uint32_t aB0 = (uint32_t)((wn * 64 + brow) * (SROW * 2)) + bcolb;

    auto load_stage = [&](int kc, int st) {
        uint32_t sb = sbase + st * STAGE_B;
        size_t ga = ((size_t)(bm + ldr) * 32 + kc * 4 + ldu2) * 16;
        size_t gb = ((size_t)(bn + ldr) * 32 + kc * 4 + ldu2) * 16;
        uint32_t so = (uint32_t)(ldr * (SROW * 2)) + ldu2 * 16;
        #pragma unroll
        for (int u = 0; u < 2; u++) {
            cp_async16(sb + so + u * 16,               GAh + ga + u * 16);
            cp_async16(sb + ARR_B + so + u * 16,       GAl + ga + u * 16);
            cp_async16(sb + 2 * ARR_B + so + u * 16,   GBh + gb + u * 16);
            cp_async16(sb + 3 * ARR_B + so + u * 16,   GBl + gb + u * 16);
        }
    };

    load_stage(0, 0);
    CP_COMMIT();

    for (int kc = 0; kc < 8; kc++) {
        int st = kc & 1;
        if (kc < 7) {
            load_stage(kc + 1, st ^ 1);
            CP_COMMIT();
            CP_WAIT1();
        } else {
            CP_WAIT0();
        }
        __syncthreads();

        uint32_t uAh = sbase + st * STAGE_B;
        uint32_t uAl = uAh + ARR_B;
        uint32_t uBh = uAh + 2 * ARR_B;
        uint32_t uBl = uAh + 3 * ARR_B;
        #pragma unroll
        for (int ks = 0; ks < 2; ks++) {
            uint32_t ah[2][4], al[2][4];
            ldsm_x4(ah[0], uAh + aA0 + ks * 32);
            ldsm_x4(ah[1], uAh + aA0 + 16 * (SROW * 2) + ks * 32);
            ldsm_x4(al[0], uAl + aA0 + ks * 32);
            ldsm_x4(al[1], uAl + aA0 + 16 * (SROW * 2) + ks * 32);
            #pragma unroll
            for (int j = 0; j < 4; j++) {
                uint32_t bh[4], bl[4];
                ldsm_x4(bh, uBh + aB0 + j * 16 * (SROW * 2) + ks * 32);
                ldsm_x4(bl, uBl + aB0 + j * 16 * (SROW * 2) + ks * 32);
                // dep spacing 4: interleave t and output column before term switch
                mma16816(acc[0][j * 2],     ah[0], bh);
                mma16816(acc[1][j * 2],     ah[1], bh);
                mma16816(acc[0][j * 2 + 1], ah[0], bh + 2);
                mma16816(acc[1][j * 2 + 1], ah[1], bh + 2);
                mma16816(acc[0][j * 2],     ah[0], bl);
                mma16816(acc[1][j * 2],     ah[1], bl);
                mma16816(acc[0][j * 2 + 1], ah[0], bl + 2);
                mma16816(acc[1][j * 2 + 1], ah[1], bl + 2);
                mma16816(acc[0][j * 2],     al[0], bh);
                mma16816(acc[1][j * 2],     al[1], bh);
                mma16816(acc[0][j * 2 + 1], al[0], bh + 2);
                mma16816(acc[1][j * 2 + 1], al[1], bh + 2);
            }
        }
        __syncthreads();
    }

    // epilogue: c-frag -> float2 stores + bias
    int crow0 = bm + wm * 32 + (lid >> 2);
    int ccol0 = bn + wn * 64 + (lid & 3) * 2;
    #pragma unroll
    for (int t = 0; t < 2; t++) {
        #pragma unroll
        for (int j = 0; j < 8; j++) {
            int col = ccol0 + j * 8;
            float b0 = __ldg(&bq[col]);
            float b1 = __ldg(&bq[col + 1]);
            int row = crow0 + t * 16;
            float2 v0 = make_float2(acc[t][j][0] + b0, acc[t][j][1] + b1);
            float2 v1 = make_float2(acc[t][j][2] + b0, acc[t][j][3] + b1);
            *(float2*)&g_qkv[(size_t)row * NOUT3 + col] = v0;
            *(float2*)&g_qkv[(size_t)(row + 8) * NOUT3 + col] = v1;
        }
    }
}

// -------- K3: per-(b,h,n) windowed attention (register-tiled) --------
__global__ void __launch_bounds__(256) k_attn(const float* __restrict__ pos_bias) {
    int blk = blockIdx.x;                              // b*4800 + h*600 + n
    int b = blk / (NHD * NWIN);
    int r = blk - b * NHD * NWIN;
    int h = r / NWIN;
    int n = r - h * NWIN;

    __shared__ float qs[WS2][36];
    __shared__ float ks[WS2][36];
    __shared__ float vs[WS2][32];
    __shared__ float S[WS2][WS2];
    __shared__ float pbs[WS2];
    int tid = threadIdx.x;
    if (tid < WS2) pbs[tid] = pos_bias[tid];

    size_t rowbase = (size_t)(b * NWIN + n) * WS2 * NOUT3 + h * HDD;
    for (int e = tid; e < WS2 * HDD; e += 256) {
        int sidx = e >> 5, d = e & 31;
        size_t rb = rowbase + (size_t)sidx * NOUT3 + d;
        qs[sidx][d] = g_qkv[rb];
        ks[sidx][d] = g_qkv[rb + 256];
        vs[sidx][d] = g_qkv[rb + 512];
    }
    __syncthreads();

    const float scale = 0.17677669529663687f;          // 1/sqrt(32)
    int pp = tid >> 2, qtr = tid & 3;
    if (pp < WS2) {
        float4 q[8];
        const float4* q4 = (const float4*)qs[pp];
        #pragma unroll
        for (int i = 0; i < 8; i++) q[i] = q4[i];
        float pb = pbs[pp];
        int cc0 = qtr * 13;
        int ccn = (qtr < 3) ? 13 : 10;
        for (int c = cc0; c < cc0 + ccn; c++) {
            const float4* k4 = (const float4*)ks[c];
            float acc = 0.f;
            #pragma unroll
            for (int i = 0; i < 8; i++) {
                float4 kv = k4[i];
                acc += q[i].x * kv.x + q[i].y * kv.y + q[i].z * kv.z + q[i].w * kv.w;
            }
            S[pp][c] = acc * scale + pb;
        }
    }
    __syncthreads();

    if (tid < WS2) {
        float mx = -1e30f;
        #pragma unroll 7
        for (int c = 0; c < WS2; c++) mx = fmaxf(mx, S[tid][c]);
        float sum = 0.f;
        #pragma unroll 7
        for (int c = 0; c < WS2; c++) { float ev = __expf(S[tid][c] - mx); S[tid][c] = ev; sum += ev; }
        float inv = 1.f / sum;
        #pragma unroll 7
        for (int c = 0; c < WS2; c++) S[tid][c] *= inv;
    }
    __syncthreads();

    // o[b,h,n,p,d] at batch-flat offset h*940800 + p*19200 + n*32 + d
    size_t obase = (size_t)b * OB_PER_B + (size_t)h * (WS2 * NWIN * HDD) + (size_t)n * HDD;
    if (pp < WS2) {
        int d0 = qtr * 8;
        float acc[8] = {0.f, 0.f, 0.f, 0.f, 0.f, 0.f, 0.f, 0.f};
        #pragma unroll 7
        for (int c = 0; c < WS2; c++) {
            float sv = S[pp][c];
            float4 va = *(const float4*)&vs[c][d0];
            float4 vb = *(const float4*)&vs[c][d0 + 4];
            acc[0] += sv * va.x; acc[1] += sv * va.y; acc[2] += sv * va.z; acc[3] += sv * va.w;
            acc[4] += sv * vb.x; acc[5] += sv * vb.y; acc[6] += sv * vb.z; acc[7] += sv * vb.w;
        }
        float4 o0 = make_float4(acc[0], acc[1], acc[2], acc[3]);
        float4 o1 = make_float4(acc[4], acc[5], acc[6], acc[7]);
        size_t ob = obase + (size_t)pp * (NWIN * HDD) + d0;
        *(float4*)&g_o[ob] = o0;
        *(float4*)&g_o[ob + 4] = o1;
    }
}

// -------- K4: conv reduce over scrambled s2 axis --------
__global__ void k_conv(const float* __restrict__ conv_w, const float* __restrict__ conv_b) {
    __shared__ float cw[WS2];
    int tid = threadIdx.x;
    if (tid < WS2) cw[tid] = conv_w[tid];
    __syncthreads();
    int idx = blockIdx.x * 256 + tid;                  // < 307200
    int b = idx / (NWIN * NC);
    int r = idx - b * (NWIN * NC);
    int n2 = r >> 8, c2 = r & 255;
    size_t base = (size_t)b * OB_PER_B + (size_t)n2 * (WS2 * NC) + c2;
    float accv = conv_b[0];
    #pragma unroll 7
    for (int s2 = 0; s2 < WS2; s2++) accv += cw[s2] * g_o[base + (size_t)s2 * NC];
    g_ypre[idx] = accv;
}

// -------- K5a: transpose w_proj --------
__global__ void k_wpt(const float* __restrict__ wp) {
    int idx = blockIdx.x * 256 + threadIdx.x;          // < 65536
    int k = idx >> 8, c = idx & 255;
    g_wpT[idx] = wp[c * NC + k];
}

// -------- K5b: y = ypre @ w_proj^T + b_proj (4 rows/block) --------
__global__ void __launch_bounds__(256) k_proj(const float* __restrict__ bp, float* __restrict__ out) {
    __shared__ float rowv[4][NC];
    int row0 = blockIdx.x * 4;
    int c = threadIdx.x;
    #pragma unroll
    for (int i = 0; i < 4; i++) rowv[i][c] = g_ypre[(size_t)(row0 + i) * NC + c];
    __syncthreads();
    float a0 = 0.f, a1 = 0.f, a2 = 0.f, a3 = 0.f;
    #pragma unroll 8
    for (int k = 0; k < NC; k++) {
        float wv = g_wpT[k * NC + c];
        a0 += rowv[0][k] * wv; a1 += rowv[1][k] * wv;
        a2 += rowv[2][k] * wv; a3 += rowv[3][k] * wv;
    }
    float bb = bp[c];
    out[(size_t)(row0 + 0) * NC + c] = a0 + bb;
    out[(size_t)(row0 + 1) * NC + c] = a1 + bb;
    out[(size_t)(row0 + 2) * NC + c] = a2 + bb;
    out[(size_t)(row0 + 3) * NC + c] = a3 + bb;
}

extern "C" void kernel_launch(void* const* d_in, const int* in_sizes, int n_in,
                              void* d_out, int out_size) {
    const float* x        = (const float*)d_in[0];
    const float* polys    = (const float*)d_in[1];
    const float* w_qkv    = (const float*)d_in[2];
    const float* b_qkv    = (const float*)d_in[3];
    const float* w_proj   = (const float*)d_in[4];
    const float* b_proj   = (const float*)d_in[5];
    const float* conv_w   = (const float*)d_in[6];
    const float* conv_b   = (const float*)d_in[7];
    const float* pos_bias = (const float*)d_in[8];
    float* out = (float*)d_out;

    static int smem_set = 0;
    if (!smem_set) {
        cudaFuncSetAttribute(k_gemm_mma, cudaFuncAttributeMaxDynamicSharedMemorySize, GSM_TOTAL);
        smem_set = 1;
    }

    dim3 gt(128, 8, 2);
    dim3 bt(32, 8);
    k_transpose_x<<<gt, bt>>>(x);
    k_sample<<<NROWS, 64>>>(polys);
    k_wconv<<<(NOUT3 * KD) / 256, 256>>>(w_qkv);
    dim3 g2(MPAD / 128, NOUT3 / 128);
    k_gemm_mma<<<g2, 256, GSM_TOTAL>>>(b_qkv);
    k_attn<<<NB * NHD * NWIN, 256>>>(pos_bias);
    k_conv<<<(NB * NWIN * NC) / 256, 256>>>(conv_w, conv_b);
    k_wpt<<<NC * NC / 256, 256>>>(w_proj);
    k_proj<<<NB * NWIN / 4, 256>>>(b_proj, out);
}

// round 9
// speedup vs baseline: 1.7663x; 1.0529x over previous
#include <cuda_runtime.h>
#include <cuda_bf16.h>
#include <cstdint>
#include <math.h>

#define NB 2
#define NQ 100
#define NC 256
#define NHW 64
#define NP 6
#define WSZ 7
#define WS2 49
#define NHD 8
#define HDD 32
#define NWIN 600            // Q*NP
#define NROWS 58800         // NB*NWIN*WS2
#define MPAD 58880          // 460*128 (GEMM M padding)
#define KD 256
#define NOUT3 768
#define OB_PER_B 7526400    // NHD*WS2*NWIN*HDD

// -------- scratch (static device globals; no runtime alloc allowed) --------
__device__ float g_xt[NB * NHW * NHW * NC];            // x transposed to (b,y,x,c)
__device__ __nv_bfloat16 g_ahi[(size_t)MPAD * KD];     // sampled features hi (bf16)
__device__ __nv_bfloat16 g_alo[(size_t)MPAD * KD];     // sampled features lo (bf16)
__device__ uint4 g_bfrag[96 * 16 * 32];                // w_qkv in MMA-fragment order
__device__ float g_qkv[(size_t)MPAD * NOUT3];          // qkv projections (fp32)
__device__ float g_o[(size_t)NB * OB_PER_B];           // attention out (scrambled-flat layout)
__device__ float g_ypre[NB * NWIN * NC];               // conv-reduced
__device__ float g_wpT[NC * NC];                       // w_proj transposed

// ======================= mma.sync / cp.async helpers (baseline ISA) =======================
__device__ __forceinline__ uint32_t smem_u32(const void* p) {
    uint32_t a;
    asm("{ .reg .u64 t; cvta.to.shared.u64 t, %1; cvt.u32.u64 %0, t; }" : "=r"(a) : "l"(p));
    return a;
}
__device__ __forceinline__ void ldsm_x4(uint32_t* r, uint32_t addr) {
    asm volatile("ldmatrix.sync.aligned.m8n8.x4.shared.b16 {%0,%1,%2,%3}, [%4];"
                 : "=r"(r[0]), "=r"(r[1]), "=r"(r[2]), "=r"(r[3]) : "r"(addr));
}
__device__ __forceinline__ void mma16816(float* c, const uint32_t* a, const uint32_t* b) {
    asm volatile("mma.sync.aligned.m16n8k16.row.col.f32.bf16.bf16.f32 "
                 "{%0,%1,%2,%3}, {%4,%5,%6,%7}, {%8,%9}, {%0,%1,%2,%3};"
                 : "+f"(c[0]), "+f"(c[1]), "+f"(c[2]), "+f"(c[3])
                 : "r"(a[0]), "r"(a[1]), "r"(a[2]), "r"(a[3]), "r"(b[0]), "r"(b[1]));
}
__device__ __forceinline__ void cp_async16(uint32_t saddr, const void* gptr) {
    asm volatile("cp.async.cg.shared.global [%0], [%1], 16;" :: "r"(saddr), "l"(gptr));
}
#define CP_COMMIT() asm volatile("cp.async.commit_group;" ::: "memory")
#define CP_WAIT1() asm volatile("cp.async.wait_group 1;" ::: "memory")
#define CP_WAIT0() asm volatile("cp.async.wait_group 0;" ::: "memory")

__device__ __forceinline__ uint32_t pack_bf2_hi(float a, float b) {
    __nv_bfloat162 t; t.x = __float2bfloat16(a); t.y = __float2bfloat16(b);
    return *(uint32_t*)&t;
}
__device__ __forceinline__ uint32_t pack_bf2_lo(float a, float b) {
    float ra = a - __bfloat162float(__float2bfloat16(a));
    float rb = b - __bfloat162float(__float2bfloat16(b));
    __nv_bfloat162 t; t.x = __float2bfloat16(ra); t.y = __float2bfloat16(rb);
    return *(uint32_t*)&t;
}

// -------- K0: x (B,C,H,W) -> xt (B,H,W,C), tiled transpose --------
__global__ void k_transpose_x(const float* __restrict__ x) {
    __shared__ float tile[32][33];
    int b = blockIdx.z;
    int c0 = blockIdx.y * 32, p0 = blockIdx.x * 32;
    #pragma unroll
    for (int i = threadIdx.y; i < 32; i += 8)
        tile[i][threadIdx.x] = x[((size_t)(b * NC + c0 + i) << 12) + p0 + threadIdx.x];
    __syncthreads();
    #pragma unroll
    for (int i = threadIdx.y; i < 32; i += 8)
        g_xt[(((size_t)b << 12) + p0 + i) * NC + c0 + threadIdx.x] = tile[threadIdx.x][i];
}

// -------- K1: poly eval + bilinear sample -> Ahi/Alo[b,n,s,c] (bf16 split) --------
__global__ void k_sample(const float* __restrict__ polys) {
    int j = blockIdx.x;                                // 0..58799 = ((b*600+n)*49+s)
    int t = threadIdx.x;                               // 0..63, 4 channels each
    int b = j / (NWIN * WS2);
    int r = j - b * (NWIN * WS2);
    int n = r / WS2;
    int s = r - n * WS2;
    int q = n / NP;
    int nid = n - q * NP;
    int m = nid * WS2 + s;
    int w = m / NP;
    int p = m - w * NP;

    const float* pc = polys + ((size_t)(b * NQ + q) * 2) * NP;
    float a = (float)p * 0.2f;
    float py = pc[0];
    #pragma unroll
    for (int i = 1; i < NP; i++) py = py * a + pc[i];
    float px = pc[NP];
    #pragma unroll
    for (int i = 1; i < NP; i++) px = px * a + pc[NP + i];
    py = 2.f * py - 1.f;
    px = 2.f * px - 1.f;

    int wy = w / WSZ, wx = w - wy * WSZ;
    float dy = (-4.0f + (float)wy * (7.0f / 6.0f)) * (2.0f / 64.0f);
    float dx = (-4.0f + (float)wx * (7.0f / 6.0f)) * (2.0f / 64.0f);
    float gy = py + dy, gx = px + dx;

    float fx = (gy + 1.f) * 0.5f * 63.f;
    float fy = (gx + 1.f) * 0.5f * 63.f;
    float x0f = floorf(fx), y0f = floorf(fy);
    float wx1 = fx - x0f, wy1 = fy - y0f;

    float vx0 = (x0f >= 0.f && x0f <= 63.f) ? 1.f : 0.f;
    float vx1 = (x0f + 1.f >= 0.f && x0f + 1.f <= 63.f) ? 1.f : 0.f;
    float vy0 = (y0f >= 0.f && y0f <= 63.f) ? 1.f : 0.f;
    float vy1 = (y0f + 1.f >= 0.f && y0f + 1.f <= 63.f) ? 1.f : 0.f;
    int xi0 = min(max((int)x0f, 0), 63);
    int xi1 = min(max((int)x0f + 1, 0), 63);
    int yi0 = min(max((int)y0f, 0), 63);
    int yi1 = min(max((int)y0f + 1, 0), 63);

    float w00 = (1.f - wy1) * (1.f - wx1) * vy0 * vx0;
    float w01 = (1.f - wy1) * wx1 * vy0 * vx1;
    float w10 = wy1 * (1.f - wx1) * vy1 * vx0;
    float w11 = wy1 * wx1 * vy1 * vx1;

    const float4* xt4 = (const float4*)g_xt;
    size_t pbase = (size_t)b * 4096;
    const float4* p00 = xt4 + (pbase + yi0 * 64 + xi0) * 64;
    const float4* p01 = xt4 + (pbase + yi0 * 64 + xi1) * 64;
    const float4* p10 = xt4 + (pbase + yi1 * 64 + xi0) * 64;
    const float4* p11 = xt4 + (pbase + yi1 * 64 + xi1) * 64;
    float4 v00 = p00[t], v01 = p01[t], v10 = p10[t], v11 = p11[t];
    float4 o;
    o.x = w00 * v00.x + w01 * v01.x + w10 * v10.x + w11 * v11.x;
    o.y = w00 * v00.y + w01 * v01.y + w10 * v10.y + w11 * v11.y;
    o.z = w00 * v00.z + w01 * v01.z + w10 * v10.z + w11 * v11.z;
    o.w = w00 * v00.w + w01 * v01.w + w10 * v10.w + w11 * v11.w;

    // two-term bf16 split
    __nv_bfloat16 h0 = __float2bfloat16(o.x), h1 = __float2bfloat16(o.y);
    __nv_bfloat16 h2 = __float2bfloat16(o.z), h3 = __float2bfloat16(o.w);
    __nv_bfloat16 l0 = __float2bfloat16(o.x - __bfloat162float(h0));
    __nv_bfloat16 l1 = __float2bfloat16(o.y - __bfloat162float(h1));
    __nv_bfloat16 l2 = __float2bfloat16(o.z - __bfloat162float(h2));
    __nv_bfloat16 l3 = __float2bfloat16(o.w - __bfloat162float(h3));
    __nv_bfloat162 hv0; hv0.x = h0; hv0.y = h1;
    __nv_bfloat162 hv1; hv1.x = h2; hv1.y = h3;
    __nv_bfloat162 lv0; lv0.x = l0; lv0.y = l1;
    __nv_bfloat162 lv1; lv1.x = l2; lv1.y = l3;
    size_t base2 = (size_t)j * 128 + t * 2;            // bf16x2 units
    ((__nv_bfloat162*)g_ahi)[base2] = hv0;
    ((__nv_bfloat162*)g_ahi)[base2 + 1] = hv1;
    ((__nv_bfloat162*)g_alo)[base2] = lv0;
    ((__nv_bfloat162*)g_alo)[base2 + 1] = lv1;
}

// -------- K1b: w_qkv -> per-lane MMA B-fragments (hi/lo packed in one uint4) --------
// g_bfrag[((nt*16 + kt)*32 + lane)] ; nt = n/8 (96), kt = k/16 (16)
// lane provides n = nt*8 + lane/4, k = kt*16 + (lane%4)*2 (+1, +8, +9)
__global__ void k_wfrag(const float* __restrict__ wq) {
    int i = blockIdx.x * 256 + threadIdx.x;            // < 49152
    int lane = i & 31;
    int kt = (i >> 5) & 15;
    int nt = i >> 9;
    int n = nt * 8 + (lane >> 2);
    int kb = kt * 16 + (lane & 3) * 2;
    const float* row = wq + (size_t)n * KD;
    float v00 = row[kb],     v01 = row[kb + 1];
    float v10 = row[kb + 8], v11 = row[kb + 9];
    uint4 bf;
    bf.x = pack_bf2_hi(v00, v01);
    bf.y = pack_bf2_hi(v10, v11);
    bf.z = pack_bf2_lo(v00, v01);
    bf.w = pack_bf2_lo(v10, v11);
    g_bfrag[i] = bf;
}

// -------- K2: HMMA GEMM, A via cp.async smem, B via fragment LDG.128 --------
// CTA tile 128x128, 8 warps (4m x 2n), warp tile 32x64, K chunk 32 (8 iters).
// 3 bf16 terms: Ah*Bh + Ah*Bl + Al*Bh. Dep spacing 4 via j-pair interleave.
#define SROW 40                     // smem row stride in bf16 (80B)
#define ARR_B (128 * SROW * 2)      // 10240 B per array
#define STAGE_B (2 * ARR_B)         // 20480 B per stage (A hi + A lo)
#define GSM_TOTAL (2 * STAGE_B)     // 40960 B

__global__ void __launch_bounds__(256, 2) k_gemm_mma(const float* __restrict__ bq) {
    extern __shared__ __align__(16) char dsm[];
    int tid = threadIdx.x;
    int wid = tid >> 5, lid = tid & 31;
    int wm = wid >> 1, wn = wid & 1;                   // 4 x 2 warp grid
    int bm = blockIdx.x * 128, bn = blockIdx.y * 128;

    float acc[2][8][4];
    #pragma unroll
    for (int t = 0; t < 2; t++)
        #pragma unroll
        for (int j = 0; j < 8; j++)
            #pragma unroll
            for (int e = 0; e < 4; e++) acc[t][j][e] = 0.f;

    uint32_t sbase = smem_u32(dsm);

    int ldr = tid >> 1;                                // 0..127 row
    int ldu2 = (tid & 1) * 2;                          // chunk pair 0 or 2

    const char* GAh = (const char*)g_ahi;
    const char* GAl = (const char*)g_alo;
    const uint4* BF = (const uint4*)g_bfrag;
    int wb = ((bn + wn * 64) >> 3) * 512 + lid;        // warp's B-frag base (uint4 units)

    int arow = lid & 15;
    int acolb = (lid >> 4) * 16;
    uint32_t aA0 = (uint32_t)((wm * 32 + arow) * (SROW * 2)) + acolb;

    auto load_stage = [&](int kc, int st) {
        uint32_t sb = sbase + st * STAGE_B;
        size_t ga = ((size_t)(bm + ldr) * 32 + kc * 4 + ldu2) * 16;
        uint32_t so = (uint32_t)(ldr * (SROW * 2)) + ldu2 * 16;
        #pragma unroll
        for (int u = 0; u < 2; u++) {
            cp_async16(sb + so + u * 16,         GAh + ga + u * 16);
            cp_async16(sb + ARR_B + so + u * 16, GAl + ga + u * 16);
        }
    };

    load_stage(0, 0);
    CP_COMMIT();

    for (int kc = 0; kc < 8; kc++) {
        int st = kc & 1;
        if (kc < 7) {
            load_stage(kc + 1, st ^ 1);
            CP_COMMIT();
            CP_WAIT1();
        } else {
            CP_WAIT0();
        }
        __syncthreads();

        uint32_t uAh = sbase + st * STAGE_B;
        uint32_t uAl = uAh + ARR_B;
        #pragma unroll
        for (int ks = 0; ks < 2; ks++) {
            int ktoff = (kc * 2 + ks) * 32;
            uint32_t ah[2][4], al[2][4];
            ldsm_x4(ah[0], uAh + aA0 + ks * 32);
            ldsm_x4(ah[1], uAh + aA0 + 16 * (SROW * 2) + ks * 32);
            ldsm_x4(al[0], uAl + aA0 + ks * 32);
            ldsm_x4(al[1], uAl + aA0 + 16 * (SROW * 2) + ks * 32);
            uint4 b0 = BF[wb + 0 * 512 + ktoff];
            uint4 b1 = BF[wb + 1 * 512 + ktoff];
            #pragma unroll
            for (int jp = 0; jp < 4; jp++) {
                uint4 n0, n1;
                if (jp < 3) {
                    n0 = BF[wb + (jp * 2 + 2) * 512 + ktoff];
                    n1 = BF[wb + (jp * 2 + 3) * 512 + ktoff];
                }
                int ja = jp * 2, jb = ja + 1;
                const uint32_t* p0 = (const uint32_t*)&b0;
                const uint32_t* p1 = (const uint32_t*)&b1;
                // hh
                mma16816(acc[0][ja], ah[0], p0);
                mma16816(acc[0][jb], ah[0], p1);
                mma16816(acc[1][ja], ah[1], p0);
                mma16816(acc[1][jb], ah[1], p1);
                // hl
                mma16816(acc[0][ja], ah[0], p0 + 2);
                mma16816(acc[0][jb], ah[0], p1 + 2);
                mma16816(acc[1][ja], ah[1], p0 + 2);
                mma16816(acc[1][jb], ah[1], p1 + 2);
                // lh
                mma16816(acc[0][ja], al[0], p0);
                mma16816(acc[0][jb], al[0], p1);
                mma16816(acc[1][ja], al[1], p0);
                mma16816(acc[1][jb], al[1], p1);
                b0 = n0; b1 = n1;
            }
        }
        __syncthreads();
    }

    // epilogue: c-frag -> float2 stores + bias
    int crow0 = bm + wm * 32 + (lid >> 2);
    int ccol0 = bn + wn * 64 + (lid & 3) * 2;
    #pragma unroll
    for (int t = 0; t < 2; t++) {
        #pragma unroll
        for (int j = 0; j < 8; j++) {
            int col = ccol0 + j * 8;
            float b0 = __ldg(&bq[col]);
            float b1 = __ldg(&bq[col + 1]);
            int row = crow0 + t * 16;
            float2 v0 = make_float2(acc[t][j][0] + b0, acc[t][j][1] + b1);
            float2 v1 = make_float2(acc[t][j][2] + b0, acc[t][j][3] + b1);
            *(float2*)&g_qkv[(size_t)row * NOUT3 + col] = v0;
            *(float2*)&g_qkv[(size_t)(row + 8) * NOUT3 + col] = v1;
        }
    }
}

// -------- K3: per-(b,h,n) windowed attention (register-tiled) --------
__global__ void __launch_bounds__(256) k_attn(const float* __restrict__ pos_bias) {
    int blk = blockIdx.x;                              // b*4800 + h*600 + n
    int b = blk / (NHD * NWIN);
    int r = blk - b * NHD * NWIN;
    int h = r / NWIN;
    int n = r - h * NWIN;

    __shared__ float qs[WS2][36];
    __shared__ float ks[WS2][36];
    __shared__ float vs[WS2][32];
    __shared__ float S[WS2][WS2];
    __shared__ float pbs[WS2];
    int tid = threadIdx.x;
    if (tid < WS2) pbs[tid] = pos_bias[tid];

    size_t rowbase = (size_t)(b * NWIN + n) * WS2 * NOUT3 + h * HDD;
    for (int e = tid; e < WS2 * HDD; e += 256) {
        int sidx = e >> 5, d = e & 31;
        size_t rb = rowbase + (size_t)sidx * NOUT3 + d;
        qs[sidx][d] = g_qkv[rb];
        ks[sidx][d] = g_qkv[rb + 256];
        vs[sidx][d] = g_qkv[rb + 512];
    }
    __syncthreads();

    const float scale = 0.17677669529663687f;          // 1/sqrt(32)
    int pp = tid >> 2, qtr = tid & 3;
    if (pp < WS2) {
        float4 q[8];
        const float4* q4 = (const float4*)qs[pp];
        #pragma unroll
        for (int i = 0; i < 8; i++) q[i] = q4[i];
        float pb = pbs[pp];
        int cc0 = qtr * 13;
        int ccn = (qtr < 3) ? 13 : 10;
        for (int c = cc0; c < cc0 + ccn; c++) {
            const float4* k4 = (const float4*)ks[c];
            float acc = 0.f;
            #pragma unroll
            for (int i = 0; i < 8; i++) {
                float4 kv = k4[i];
                acc += q[i].x * kv.x + q[i].y * kv.y + q[i].z * kv.z + q[i].w * kv.w;
            }
            S[pp][c] = acc * scale + pb;
        }
    }
    __syncthreads();

    if (tid < WS2) {
        float mx = -1e30f;
        #pragma unroll 7
        for (int c = 0; c < WS2; c++) mx = fmaxf(mx, S[tid][c]);
        float sum = 0.f;
        #pragma unroll 7
        for (int c = 0; c < WS2; c++) { float ev = __expf(S[tid][c] - mx); S[tid][c] = ev; sum += ev; }
        float inv = 1.f / sum;
        #pragma unroll 7
        for (int c = 0; c < WS2; c++) S[tid][c] *= inv;
    }
    __syncthreads();

    // o[b,h,n,p,d] at batch-flat offset h*940800 + p*19200 + n*32 + d
    size_t obase = (size_t)b * OB_PER_B + (size_t)h * (WS2 * NWIN * HDD) + (size_t)n * HDD;
    if (pp < WS2) {
        int d0 = qtr * 8;
        float acc[8] = {0.f, 0.f, 0.f, 0.f, 0.f, 0.f, 0.f, 0.f};
        #pragma unroll 7
        for (int c = 0; c < WS2; c++) {
            float sv = S[pp][c];
            float4 va = *(const float4*)&vs[c][d0];
            float4 vb = *(const float4*)&vs[c][d0 + 4];
            acc[0] += sv * va.x; acc[1] += sv * va.y; acc[2] += sv * va.z; acc[3] += sv * va.w;
            acc[4] += sv * vb.x; acc[5] += sv * vb.y; acc[6] += sv * vb.z; acc[7] += sv * vb.w;
        }
        float4 o0 = make_float4(acc[0], acc[1], acc[2], acc[3]);
        float4 o1 = make_float4(acc[4], acc[5], acc[6], acc[7]);
        size_t ob = obase + (size_t)pp * (NWIN * HDD) + d0;
        *(float4*)&g_o[ob] = o0;
        *(float4*)&g_o[ob + 4] = o1;
    }
}

// -------- K4: conv reduce over scrambled s2 axis --------
__global__ void k_conv(const float* __restrict__ conv_w, const float* __restrict__ conv_b) {
    __shared__ float cw[WS2];
    int tid = threadIdx.x;
    if (tid < WS2) cw[tid] = conv_w[tid];
    __syncthreads();
    int idx = blockIdx.x * 256 + tid;                  // < 307200
    int b = idx / (NWIN * NC);
    int r = idx - b * (NWIN * NC);
    int n2 = r >> 8, c2 = r & 255;
    size_t base = (size_t)b * OB_PER_B + (size_t)n2 * (WS2 * NC) + c2;
    float accv = conv_b[0];
    #pragma unroll 7
    for (int s2 = 0; s2 < WS2; s2++) accv += cw[s2] * g_o[base + (size_t)s2 * NC];
    g_ypre[idx] = accv;
}

// -------- K5a: transpose w_proj --------
__global__ void k_wpt(const float* __restrict__ wp) {
    int idx = blockIdx.x * 256 + threadIdx.x;          // < 65536
    int k = idx >> 8, c = idx & 255;
    g_wpT[idx] = wp[c * NC + k];
}

// -------- K5b: y = ypre @ w_proj^T + b_proj (4 rows/block) --------
__global__ void __launch_bounds__(256) k_proj(const float* __restrict__ bp, float* __restrict__ out) {
    __shared__ float rowv[4][NC];
    int row0 = blockIdx.x * 4;
    int c = threadIdx.x;
    #pragma unroll
    for (int i = 0; i < 4; i++) rowv[i][c] = g_ypre[(size_t)(row0 + i) * NC + c];
    __syncthreads();
    float a0 = 0.f, a1 = 0.f, a2 = 0.f, a3 = 0.f;
    #pragma unroll 8
    for (int k = 0; k < NC; k++) {
        float wv = g_wpT[k * NC + c];
        a0 += rowv[0][k] * wv; a1 += rowv[1][k] * wv;
        a2 += rowv[2][k] * wv; a3 += rowv[3][k] * wv;
    }
    float bb = bp[c];
    out[(size_t)(row0 + 0) * NC + c] = a0 + bb;
    out[(size_t)(row0 + 1) * NC + c] = a1 + bb;
    out[(size_t)(row0 + 2) * NC + c] = a2 + bb;
    out[(size_t)(row0 + 3) * NC + c] = a3 + bb;
}

extern "C" void kernel_launch(void* const* d_in, const int* in_sizes, int n_in,
                              void* d_out, int out_size) {
    const float* x        = (const float*)d_in[0];
    const float* polys    = (const float*)d_in[1];
    const float* w_qkv    = (const float*)d_in[2];
    const float* b_qkv    = (const float*)d_in[3];
    const float* w_proj   = (const float*)d_in[4];
    const float* b_proj   = (const float*)d_in[5];
    const float* conv_w   = (const float*)d_in[6];
    const float* conv_b   = (const float*)d_in[7];
    const float* pos_bias = (const float*)d_in[8];
    float* out = (float*)d_out;

    static int smem_set = 0;
    if (!smem_set) {
        cudaFuncSetAttribute(k_gemm_mma, cudaFuncAttributeMaxDynamicSharedMemorySize, GSM_TOTAL);
        smem_set = 1;
    }

    dim3 gt(128, 8, 2);
    dim3 bt(32, 8);
    k_transpose_x<<<gt, bt>>>(x);
    k_sample<<<NROWS, 64>>>(polys);
    k_wfrag<<<(96 * 16 * 32) / 256, 256>>>(w_qkv);
    dim3 g2(MPAD / 128, NOUT3 / 128);
    k_gemm_mma<<<g2, 256, GSM_TOTAL>>>(b_qkv);
    k_attn<<<NB * NHD * NWIN, 256>>>(pos_bias);
    k_conv<<<(NB * NWIN * NC) / 256, 256>>>(conv_w, conv_b);
    k_wpt<<<NC * NC / 256, 256>>>(w_proj);
    k_proj<<<NB * NWIN / 4, 256>>>(b_proj, out);
}

// round 10
// speedup vs baseline: 1.7669x; 1.0003x over previous
#include <cuda_runtime.h>
#include <cuda_bf16.h>
#include <cstdint>
#include <math.h>

#define NB 2
#define NQ 100
#define NC 256
#define NHW 64
#define NP 6
#define WSZ 7
#define WS2 49
#define NHD 8
#define HDD 32
#define NWIN 600            // Q*NP
#define NROWS 58800         // NB*NWIN*WS2
#define MPAD 58880          // 460*128 (GEMM M padding)
#define KD 256
#define NOUT3 768
#define OB_PER_B 7526400    // NHD*WS2*NWIN*HDD

// -------- scratch (static device globals; no runtime alloc allowed) --------
__device__ float g_xt[NB * NHW * NHW * NC];            // x transposed to (b,y,x,c)
__device__ __nv_bfloat16 g_ahi[(size_t)MPAD * KD];     // sampled features hi (bf16)
__device__ __nv_bfloat16 g_alo[(size_t)MPAD * KD];     // sampled features lo (bf16)
__device__ uint4 g_bfrag[96 * 16 * 32];                // w_qkv in MMA-fragment order
__device__ __nv_bfloat16 g_qh[(size_t)MPAD * NOUT3];   // qkv hi (bf16)
__device__ __nv_bfloat16 g_ql[(size_t)MPAD * NOUT3];   // qkv lo (bf16)
__device__ float g_o[(size_t)NB * OB_PER_B];           // attention out (scrambled-flat layout)
__device__ float g_ypre[NB * NWIN * NC];               // conv-reduced
__device__ float g_wpT[NC * NC];                       // w_proj transposed

// ======================= mma.sync / cp.async helpers (baseline ISA) =======================
__device__ __forceinline__ uint32_t smem_u32(const void* p) {
    uint32_t a;
    asm("{ .reg .u64 t; cvta.to.shared.u64 t, %1; cvt.u32.u64 %0, t; }" : "=r"(a) : "l"(p));
    return a;
}
__device__ __forceinline__ void ldsm_x4(uint32_t* r, uint32_t addr) {
    asm volatile("ldmatrix.sync.aligned.m8n8.x4.shared.b16 {%0,%1,%2,%3}, [%4];"
                 : "=r"(r[0]), "=r"(r[1]), "=r"(r[2]), "=r"(r[3]) : "r"(addr));
}
__device__ __forceinline__ void mma16816(float* c, const uint32_t* a, const uint32_t* b) {
    asm volatile("mma.sync.aligned.m16n8k16.row.col.f32.bf16.bf16.f32 "
                 "{%0,%1,%2,%3}, {%4,%5,%6,%7}, {%8,%9}, {%0,%1,%2,%3};"
                 : "+f"(c[0]), "+f"(c[1]), "+f"(c[2]), "+f"(c[3])
                 : "r"(a[0]), "r"(a[1]), "r"(a[2]), "r"(a[3]), "r"(b[0]), "r"(b[1]));
}
__device__ __forceinline__ void cp_async16(uint32_t saddr, const void* gptr) {
    asm volatile("cp.async.cg.shared.global [%0], [%1], 16;" :: "r"(saddr), "l"(gptr));
}
#define CP_COMMIT() asm volatile("cp.async.commit_group;" ::: "memory")
#define CP_WAIT1() asm volatile("cp.async.wait_group 1;" ::: "memory")
#define CP_WAIT0() asm volatile("cp.async.wait_group 0;" ::: "memory")

__device__ __forceinline__ uint32_t pack_bf2_hi(float a, float b) {
    __nv_bfloat162 t; t.x = __float2bfloat16(a); t.y = __float2bfloat16(b);
    return *(uint32_t*)&t;
}
__device__ __forceinline__ uint32_t pack_bf2_lo(float a, float b) {
    float ra = a - __bfloat162float(__float2bfloat16(a));
    float rb = b - __bfloat162float(__float2bfloat16(b));
    __nv_bfloat162 t; t.x = __float2bfloat16(ra); t.y = __float2bfloat16(rb);
    return *(uint32_t*)&t;
}

// -------- K0: x (B,C,H,W) -> xt (B,H,W,C), tiled transpose --------
__global__ void k_transpose_x(const float* __restrict__ x) {
    __shared__ float tile[32][33];
    int b = blockIdx.z;
    int c0 = blockIdx.y * 32, p0 = blockIdx.x * 32;
    #pragma unroll
    for (int i = threadIdx.y; i < 32; i += 8)
        tile[i][threadIdx.x] = x[((size_t)(b * NC + c0 + i) << 12) + p0 + threadIdx.x];
    __syncthreads();
    #pragma unroll
    for (int i = threadIdx.y; i < 32; i += 8)
        g_xt[(((size_t)b << 12) + p0 + i) * NC + c0 + threadIdx.x] = tile[threadIdx.x][i];
}

// -------- K1: poly eval + bilinear sample -> Ahi/Alo[b,n,s,c] (bf16 split) --------
__global__ void k_sample(const float* __restrict__ polys) {
    int j = blockIdx.x;                                // 0..58799 = ((b*600+n)*49+s)
    int t = threadIdx.x;                               // 0..63, 4 channels each
    int b = j / (NWIN * WS2);
    int r = j - b * (NWIN * WS2);
    int n = r / WS2;
    int s = r - n * WS2;
    int q = n / NP;
    int nid = n - q * NP;
    int m = nid * WS2 + s;
    int w = m / NP;
    int p = m - w * NP;

    const float* pc = polys + ((size_t)(b * NQ + q) * 2) * NP;
    float a = (float)p * 0.2f;
    float py = pc[0];
    #pragma unroll
    for (int i = 1; i < NP; i++) py = py * a + pc[i];
    float px = pc[NP];
    #pragma unroll
    for (int i = 1; i < NP; i++) px = px * a + pc[NP + i];
    py = 2.f * py - 1.f;
    px = 2.f * px - 1.f;

    int wy = w / WSZ, wx = w - wy * WSZ;
    float dy = (-4.0f + (float)wy * (7.0f / 6.0f)) * (2.0f / 64.0f);
    float dx = (-4.0f + (float)wx * (7.0f / 6.0f)) * (2.0f / 64.0f);
    float gy = py + dy, gx = px + dx;

    float fx = (gy + 1.f) * 0.5f * 63.f;
    float fy = (gx + 1.f) * 0.5f * 63.f;
    float x0f = floorf(fx), y0f = floorf(fy);
    float wx1 = fx - x0f, wy1 = fy - y0f;

    float vx0 = (x0f >= 0.f && x0f <= 63.f) ? 1.f : 0.f;
    float vx1 = (x0f + 1.f >= 0.f && x0f + 1.f <= 63.f) ? 1.f : 0.f;
    float vy0 = (y0f >= 0.f && y0f <= 63.f) ? 1.f : 0.f;
    float vy1 = (y0f + 1.f >= 0.f && y0f + 1.f <= 63.f) ? 1.f : 0.f;
    int xi0 = min(max((int)x0f, 0), 63);
    int xi1 = min(max((int)x0f + 1, 0), 63);
    int yi0 = min(max((int)y0f, 0), 63);
    int yi1 = min(max((int)y0f + 1, 0), 63);

    float w00 = (1.f - wy1) * (1.f - wx1) * vy0 * vx0;
    float w01 = (1.f - wy1) * wx1 * vy0 * vx1;
    float w10 = wy1 * (1.f - wx1) * vy1 * vx0;
    float w11 = wy1 * wx1 * vy1 * vx1;

    const float4* xt4 = (const float4*)g_xt;
    size_t pbase = (size_t)b * 4096;
    const float4* p00 = xt4 + (pbase + yi0 * 64 + xi0) * 64;
    const float4* p01 = xt4 + (pbase + yi0 * 64 + xi1) * 64;
    const float4* p10 = xt4 + (pbase + yi1 * 64 + xi0) * 64;
    const float4* p11 = xt4 + (pbase + yi1 * 64 + xi1) * 64;
    float4 v00 = p00[t], v01 = p01[t], v10 = p10[t], v11 = p11[t];
    float4 o;
    o.x = w00 * v00.x + w01 * v01.x + w10 * v10.x + w11 * v11.x;
    o.y = w00 * v00.y + w01 * v01.y + w10 * v10.y + w11 * v11.y;
    o.z = w00 * v00.z + w01 * v01.z + w10 * v10.z + w11 * v11.z;
    o.w = w00 * v00.w + w01 * v01.w + w10 * v10.w + w11 * v11.w;

    uint2 hv, lv;
    hv.x = pack_bf2_hi(o.x, o.y); hv.y = pack_bf2_hi(o.z, o.w);
    lv.x = pack_bf2_lo(o.x, o.y); lv.y = pack_bf2_lo(o.z, o.w);
    size_t base2 = (size_t)j * 64 + t;                 // uint2 units
    ((uint2*)g_ahi)[base2] = hv;
    ((uint2*)g_alo)[base2] = lv;
}

// -------- K1b: w_qkv -> per-lane MMA B-fragments (hi/lo packed in one uint4) --------
__global__ void k_wfrag(const float* __restrict__ wq) {
    int i = blockIdx.x * 256 + threadIdx.x;            // < 49152
    int lane = i & 31;
    int kt = (i >> 5) & 15;
    int nt = i >> 9;
    int n = nt * 8 + (lane >> 2);
    int kb = kt * 16 + (lane & 3) * 2;
    const float* row = wq + (size_t)n * KD;
    float v00 = row[kb],     v01 = row[kb + 1];
    float v10 = row[kb + 8], v11 = row[kb + 9];
    uint4 bf;
    bf.x = pack_bf2_hi(v00, v01);
    bf.y = pack_bf2_hi(v10, v11);
    bf.z = pack_bf2_lo(v00, v01);
    bf.w = pack_bf2_lo(v10, v11);
    g_bfrag[i] = bf;
}

// -------- K2: HMMA GEMM, A via cp.async smem, B via fragment LDG.128 --------
#define SROW 40                     // smem row stride in bf16 (80B)
#define ARR_B (128 * SROW * 2)      // 10240 B per array
#define STAGE_B (2 * ARR_B)         // 20480 B per stage (A hi + A lo)
#define GSM_TOTAL (2 * STAGE_B)     // 40960 B

__global__ void __launch_bounds__(256, 2) k_gemm_mma(const float* __restrict__ bq) {
    extern __shared__ __align__(16) char dsm[];
    int tid = threadIdx.x;
    int wid = tid >> 5, lid = tid & 31;
    int wm = wid >> 1, wn = wid & 1;                   // 4 x 2 warp grid
    int bm = blockIdx.x * 128, bn = blockIdx.y * 128;

    float acc[2][8][4];
    #pragma unroll
    for (int t = 0; t < 2; t++)
        #pragma unroll
        for (int j = 0; j < 8; j++)
            #pragma unroll
            for (int e = 0; e < 4; e++) acc[t][j][e] = 0.f;

    uint32_t sbase = smem_u32(dsm);

    int ldr = tid >> 1;
    int ldu2 = (tid & 1) * 2;

    const char* GAh = (const char*)g_ahi;
    const char* GAl = (const char*)g_alo;
    const uint4* BF = (const uint4*)g_bfrag;
    int wb = ((bn + wn * 64) >> 3) * 512 + lid;

    int arow = lid & 15;
    int acolb = (lid >> 4) * 16;
    uint32_t aA0 = (uint32_t)((wm * 32 + arow) * (SROW * 2)) + acolb;

    auto load_stage = [&](int kc, int st) {
        uint32_t sb = sbase + st * STAGE_B;
        size_t ga = ((size_t)(bm + ldr) * 32 + kc * 4 + ldu2) * 16;
        uint32_t so = (uint32_t)(ldr * (SROW * 2)) + ldu2 * 16;
        #pragma unroll
        for (int u = 0; u < 2; u++) {
            cp_async16(sb + so + u * 16,         GAh + ga + u * 16);
            cp_async16(sb + ARR_B + so + u * 16, GAl + ga + u * 16);
        }
    };

    load_stage(0, 0);
    CP_COMMIT();

    for (int kc = 0; kc < 8; kc++) {
        int st = kc & 1;
        if (kc < 7) {
            load_stage(kc + 1, st ^ 1);
            CP_COMMIT();
            CP_WAIT1();
        } else {
            CP_WAIT0();
        }
        __syncthreads();

        uint32_t uAh = sbase + st * STAGE_B;
        uint32_t uAl = uAh + ARR_B;
        #pragma unroll
        for (int ks = 0; ks < 2; ks++) {
            int ktoff = (kc * 2 + ks) * 32;
            uint32_t ah[2][4], al[2][4];
            ldsm_x4(ah[0], uAh + aA0 + ks * 32);
            ldsm_x4(ah[1], uAh + aA0 + 16 * (SROW * 2) + ks * 32);
            ldsm_x4(al[0], uAl + aA0 + ks * 32);
            ldsm_x4(al[1], uAl + aA0 + 16 * (SROW * 2) + ks * 32);
            uint4 b0 = BF[wb + 0 * 512 + ktoff];
            uint4 b1 = BF[wb + 1 * 512 + ktoff];
            #pragma unroll
            for (int jp = 0; jp < 4; jp++) {
                uint4 n0, n1;
                if (jp < 3) {
                    n0 = BF[wb + (jp * 2 + 2) * 512 + ktoff];
                    n1 = BF[wb + (jp * 2 + 3) * 512 + ktoff];
                }
                int ja = jp * 2, jb = ja + 1;
                const uint32_t* p0 = (const uint32_t*)&b0;
                const uint32_t* p1 = (const uint32_t*)&b1;
                mma16816(acc[0][ja], ah[0], p0);
                mma16816(acc[0][jb], ah[0], p1);
                mma16816(acc[1][ja], ah[1], p0);
                mma16816(acc[1][jb], ah[1], p1);
                mma16816(acc[0][ja], ah[0], p0 + 2);
                mma16816(acc[0][jb], ah[0], p1 + 2);
                mma16816(acc[1][ja], ah[1], p0 + 2);
                mma16816(acc[1][jb], ah[1], p1 + 2);
                mma16816(acc[0][ja], al[0], p0);
                mma16816(acc[0][jb], al[0], p1);
                mma16816(acc[1][ja], al[1], p0);
                mma16816(acc[1][jb], al[1], p1);
                b0 = n0; b1 = n1;
            }
        }
        __syncthreads();
    }

    // epilogue: c-frag + bias -> bf16 hi/lo stores
    int crow0 = bm + wm * 32 + (lid >> 2);
    int ccol0 = bn + wn * 64 + (lid & 3) * 2;
    #pragma unroll
    for (int t = 0; t < 2; t++) {
        #pragma unroll
        for (int j = 0; j < 8; j++) {
            int col = ccol0 + j * 8;
            float b0 = __ldg(&bq[col]);
            float b1 = __ldg(&bq[col + 1]);
            int row = crow0 + t * 16;
            float v00 = acc[t][j][0] + b0, v01 = acc[t][j][1] + b1;
            float v10 = acc[t][j][2] + b0, v11 = acc[t][j][3] + b1;
            *(uint32_t*)&g_qh[(size_t)row * NOUT3 + col] = pack_bf2_hi(v00, v01);
            *(uint32_t*)&g_ql[(size_t)row * NOUT3 + col] = pack_bf2_lo(v00, v01);
            *(uint32_t*)&g_qh[(size_t)(row + 8) * NOUT3 + col] = pack_bf2_hi(v10, v11);
            *(uint32_t*)&g_ql[(size_t)(row + 8) * NOUT3 + col] = pack_bf2_lo(v10, v11);
        }
    }
}

// -------- K3: HMMA windowed attention, one (b,h,n) per block, 128 threads --------
// smem regions (bytes):
#define ATT_QH 0            // 64 x 80B  (later PH: 64 x 144B = 9216 <= 10240)
#define ATT_QL 5120
#define ATT_KH 10240        // (later PL)
#define ATT_KL 15360
#define ATT_VTH 20480       // 32 x 144B
#define ATT_VTL 25088
#define ATT_S 29696         // 64 x 68 floats = 17408 (reused as O: 64 x 36 floats)
#define ATT_PH 0
#define ATT_PL 10240
#define ATT_SM 47104
#define SSTR 68

__global__ void __launch_bounds__(128) k_attn_mma(const float* __restrict__ pos_bias) {
    extern __shared__ __align__(16) char sma[];
    int tid = threadIdx.x;
    int wid = tid >> 5, lid = tid & 31;
    int blk = blockIdx.x;
    int b = blk / (NHD * NWIN);
    int r = blk - b * NHD * NWIN;
    int h = r / NWIN;
    int n = r - h * NWIN;
    uint32_t sb = smem_u32(sma);

    // 1. zero q/k/vT regions (padding rows/cols must be 0, never NaN)
    {
        uint4 z = make_uint4(0, 0, 0, 0);
        for (int i = tid; i < 1856; i += 128) *(uint4*)(sma + i * 16) = z;
    }
    __syncthreads();

    // 2. fill q/k (rows<49) and transposed v
    const char* GH = (const char*)g_qh;
    const char* GL = (const char*)g_ql;
    size_t rowb0 = (size_t)((b * NWIN + n) * WS2) * (NOUT3 * 2);
    int hb = h * 64;
    for (int idx = tid; idx < 196; idx += 128) {
        int row = idx >> 2, u = idx & 3;
        size_t gq = rowb0 + (size_t)row * (NOUT3 * 2) + hb + u * 16;
        *(uint4*)(sma + ATT_QH + row * 80 + u * 16) = *(const uint4*)(GH + gq);
        *(uint4*)(sma + ATT_QL + row * 80 + u * 16) = *(const uint4*)(GL + gq);
        *(uint4*)(sma + ATT_KH + row * 80 + u * 16) = *(const uint4*)(GH + gq + 512);
        *(uint4*)(sma + ATT_KL + row * 80 + u * 16) = *(const uint4*)(GL + gq + 512);
    }
    for (int idx = tid; idx < 784; idx += 128) {       // vT: [d=32][c=64 pad]
        int c = idx >> 4, u = idx & 15;
        size_t gv = rowb0 + (size_t)c * (NOUT3 * 2) + 1024 + hb + u * 4;
        uint32_t vh = *(const uint32_t*)(GH + gv);
        uint32_t vl = *(const uint32_t*)(GL + gv);
        __nv_bfloat162 vh2 = *(__nv_bfloat162*)&vh;
        __nv_bfloat162 vl2 = *(__nv_bfloat162*)&vl;
        __nv_bfloat16* th = (__nv_bfloat16*)(sma + ATT_VTH);
        __nv_bfloat16* tl = (__nv_bfloat16*)(sma + ATT_VTL);
        th[(2 * u) * 72 + c] = vh2.x; th[(2 * u + 1) * 72 + c] = vh2.y;
        tl[(2 * u) * 72 + c] = vl2.x; tl[(2 * u + 1) * 72 + c] = vl2.y;
    }
    __syncthreads();

    // 3. S = q k^T via HMMA (3-term hi/lo)
    {
        float accs[8][4];
        #pragma unroll
        for (int j = 0; j < 8; j++)
            #pragma unroll
            for (int e = 0; e < 4; e++) accs[j][e] = 0.f;
        int arow = lid & 15, acolb = (lid >> 4) * 16;
        int brow = ((lid >> 4) & 1) * 8 + (lid & 7);
        int bcolb = ((lid >> 3) & 1) * 16;
        uint32_t aQh = sb + ATT_QH + (wid * 16 + arow) * 80 + acolb;
        uint32_t aQl = sb + ATT_QL + (wid * 16 + arow) * 80 + acolb;
        uint32_t aKh = sb + ATT_KH + brow * 80 + bcolb;
        uint32_t aKl = sb + ATT_KL + brow * 80 + bcolb;
        #pragma unroll
        for (int ks = 0; ks < 2; ks++) {
            uint32_t ah[4], al[4];
            ldsm_x4(ah, aQh + ks * 32);
            ldsm_x4(al, aQl + ks * 32);
            #pragma unroll
            for (int g = 0; g < 4; g++) {
                uint32_t bh[4], bl[4];
                ldsm_x4(bh, aKh + g * 16 * 80 + ks * 32);
                ldsm_x4(bl, aKl + g * 16 * 80 + ks * 32);
                mma16816(accs[g * 2],     ah, bh);
                mma16816(accs[g * 2 + 1], ah, bh + 2);
                mma16816(accs[g * 2],     ah, bl);
                mma16816(accs[g * 2 + 1], ah, bl + 2);
                mma16816(accs[g * 2],     al, bh);
                mma16816(accs[g * 2 + 1], al, bh + 2);
            }
        }
        float* S = (float*)(sma + ATT_S);
        int srow = wid * 16 + (lid >> 2), scol = (lid & 3) * 2;
        #pragma unroll
        for (int j = 0; j < 8; j++) {
            *(float2*)&S[srow * SSTR + j * 8 + scol]       = make_float2(accs[j][0], accs[j][1]);
            *(float2*)&S[(srow + 8) * SSTR + j * 8 + scol] = make_float2(accs[j][2], accs[j][3]);
        }
    }
    __syncthreads();

    // 4. zero P regions (overlays dead q/k)
    {
        uint4 z = make_uint4(0, 0, 0, 0);
        for (int i = tid; i < 1280; i += 128) *(uint4*)(sma + i * 16) = z;
    }
    __syncthreads();

    // 5. fp32 softmax per row p (<49), write P as bf16 hi/lo
    if (tid < WS2) {
        float* S = (float*)(sma + ATT_S) + tid * SSTR;
        const float scale = 0.17677669529663687f;
        float pb = pos_bias[tid];
        float mx = -1e30f;
        #pragma unroll 7
        for (int c = 0; c < WS2; c++) { float v = S[c] * scale + pb; S[c] = v; mx = fmaxf(mx, v); }
        float sum = 0.f;
        #pragma unroll 7
        for (int c = 0; c < WS2; c++) { float e = __expf(S[c] - mx); S[c] = e; sum += e; }
        float inv = 1.f / sum;
        __nv_bfloat16* PH = (__nv_bfloat16*)(sma + ATT_PH) + tid * 72;
        __nv_bfloat16* PL = (__nv_bfloat16*)(sma + ATT_PL) + tid * 72;
        #pragma unroll 7
        for (int c = 0; c < WS2; c++) {
            float p = S[c] * inv;
            __nv_bfloat16 hi = __float2bfloat16(p);
            PH[c] = hi;
            PL[c] = __float2bfloat16(p - __bfloat162float(hi));
        }
    }
    __syncthreads();

    // 6. O = P V via HMMA (3-term), frags staged into smem (reuses S region)
    {
        float acco[4][4];
        #pragma unroll
        for (int j = 0; j < 4; j++)
            #pragma unroll
            for (int e = 0; e < 4; e++) acco[j][e] = 0.f;
        int arow = lid & 15, acolb = (lid >> 4) * 16;
        int brow = ((lid >> 4) & 1) * 8 + (lid & 7);
        int bcolb = ((lid >> 3) & 1) * 16;
        uint32_t aPh = sb + ATT_PH + (wid * 16 + arow) * 144 + acolb;
        uint32_t aPl = sb + ATT_PL + (wid * 16 + arow) * 144 + acolb;
        uint32_t aVh = sb + ATT_VTH + brow * 144 + bcolb;
        uint32_t aVl = sb + ATT_VTL + brow * 144 + bcolb;
        #pragma unroll
        for (int ks = 0; ks < 4; ks++) {
            uint32_t ph[4], pl[4];
            ldsm_x4(ph, aPh + ks * 32);
            ldsm_x4(pl, aPl + ks * 32);
            #pragma unroll
            for (int g = 0; g < 2; g++) {
                uint32_t vh[4], vl[4];
                ldsm_x4(vh, aVh + g * 16 * 144 + ks * 32);
                ldsm_x4(vl, aVl + g * 16 * 144 + ks * 32);
                mma16816(acco[g * 2],     ph, vh);
                mma16816(acco[g * 2 + 1], ph, vh + 2);
                mma16816(acco[g * 2],     ph, vl);
                mma16816(acco[g * 2 + 1], ph, vl + 2);
                mma16816(acco[g * 2],     pl, vh);
                mma16816(acco[g * 2 + 1], pl, vh + 2);
            }
        }
        float* O = (float*)(sma + ATT_S);
        int orow = wid * 16 + (lid >> 2), ocol = (lid & 3) * 2;
        #pragma unroll
        for (int j = 0; j < 4; j++) {
            *(float2*)&O[orow * 36 + j * 8 + ocol]       = make_float2(acco[j][0], acco[j][1]);
            *(float2*)&O[(orow + 8) * 36 + j * 8 + ocol] = make_float2(acco[j][2], acco[j][3]);
        }
    }
    __syncthreads();

    // 7. store o[p<49][d<32] to scrambled-flat g_o
    size_t obase = (size_t)b * OB_PER_B + (size_t)h * (WS2 * NWIN * HDD) + (size_t)n * HDD;
    const float* O = (const float*)(sma + ATT_S);
    for (int idx = tid; idx < WS2 * 8; idx += 128) {
        int p = idx >> 3, d4 = (idx & 7) * 4;
        float4 v = *(const float4*)&O[p * 36 + d4];
        *(float4*)&g_o[obase + (size_t)p * (NWIN * HDD) + d4] = v;
    }
}

// -------- K4: conv reduce over scrambled s2 axis --------
__global__ void k_conv(const float* __restrict__ conv_w, const float* __restrict__ conv_b) {
    __shared__ float cw[WS2];
    int tid = threadIdx.x;
    if (tid < WS2) cw[tid] = conv_w[tid];
    __syncthreads();
    int idx = blockIdx.x * 256 + tid;                  // < 307200
    int b = idx / (NWIN * NC);
    int r = idx - b * (NWIN * NC);
    int n2 = r >> 8, c2 = r & 255;
    size_t base = (size_t)b * OB_PER_B + (size_t)n2 * (WS2 * NC) + c2;
    float accv = conv_b[0];
    #pragma unroll 7
    for (int s2 = 0; s2 < WS2; s2++) accv += cw[s2] * g_o[base + (size_t)s2 * NC];
    g_ypre[idx] = accv;
}

// -------- K5a: transpose w_proj --------
__global__ void k_wpt(const float* __restrict__ wp) {
    int idx = blockIdx.x * 256 + threadIdx.x;          // < 65536
    int k = idx >> 8, c = idx & 255;
    g_wpT[idx] = wp[c * NC + k];
}

// -------- K5b: y = ypre @ w_proj^T + b_proj (4 rows/block) --------
__global__ void __launch_bounds__(256) k_proj(const float* __restrict__ bp, float* __restrict__ out) {
    __shared__ float rowv[4][NC];
    int row0 = blockIdx.x * 4;
    int c = threadIdx.x;
    #pragma unroll
    for (int i = 0; i < 4; i++) rowv[i][c] = g_ypre[(size_t)(row0 + i) * NC + c];
    __syncthreads();
    float a0 = 0.f, a1 = 0.f, a2 = 0.f, a3 = 0.f;
    #pragma unroll 8
    for (int k = 0; k < NC; k++) {
        float wv = g_wpT[k * NC + c];
        a0 += rowv[0][k] * wv; a1 += rowv[1][k] * wv;
        a2 += rowv[2][k] * wv; a3 += rowv[3][k] * wv;
    }
    float bb = bp[c];
    out[(size_t)(row0 + 0) * NC + c] = a0 + bb;
    out[(size_t)(row0 + 1) * NC + c] = a1 + bb;
    out[(size_t)(row0 + 2) * NC + c] = a2 + bb;
    out[(size_t)(row0 + 3) * NC + c] = a3 + bb;
}

extern "C" void kernel_launch(void* const* d_in, const int* in_sizes, int n_in,
                              void* d_out, int out_size) {
    const float* x        = (const float*)d_in[0];
    const float* polys    = (const float*)d_in[1];
    const float* w_qkv    = (const float*)d_in[2];
    const float* b_qkv    = (const float*)d_in[3];
    const float* w_proj   = (const float*)d_in[4];
    const float* b_proj   = (const float*)d_in[5];
    const float* conv_w   = (const float*)d_in[6];
    const float* conv_b   = (const float*)d_in[7];
    const float* pos_bias = (const float*)d_in[8];
    float* out = (float*)d_out;

    static int smem_set = 0;
    if (!smem_set) {
        cudaFuncSetAttribute(k_gemm_mma, cudaFuncAttributeMaxDynamicSharedMemorySize, GSM_TOTAL);
        cudaFuncSetAttribute(k_attn_mma, cudaFuncAttributeMaxDynamicSharedMemorySize, ATT_SM);
        smem_set = 1;
    }

    dim3 gt(128, 8, 2);
    dim3 bt(32, 8);
    k_transpose_x<<<gt, bt>>>(x);
    k_sample<<<NROWS, 64>>>(polys);
    k_wfrag<<<(96 * 16 * 32) / 256, 256>>>(w_qkv);
    dim3 g2(MPAD / 128, NOUT3 / 128);
    k_gemm_mma<<<g2, 256, GSM_TOTAL>>>(b_qkv);
    k_attn_mma<<<NB * NHD * NWIN, 128, ATT_SM>>>(pos_bias);
    k_conv<<<(NB * NWIN * NC) / 256, 256>>>(conv_w, conv_b);
    k_wpt<<<NC * NC / 256, 256>>>(w_proj);
    k_proj<<<NB * NWIN / 4, 256>>>(b_proj, out);
}

// round 11
// speedup vs baseline: 1.8304x; 1.0359x over previous
#include <cuda_runtime.h>
#include <cuda_bf16.h>
#include <cstdint>
#include <math.h>

#define NB 2
#define NQ 100
#define NC 256
#define NHW 64
#define NP 6
#define WSZ 7
#define WS2 49
#define NHD 8
#define HDD 32
#define NWIN 600            // Q*NP
#define NROWS 58800         // NB*NWIN*WS2
#define MPAD 58880          // 460*128 (GEMM M padding)
#define KD 256
#define NOUT3 768
#define OB_PER_B 7526400    // NHD*WS2*NWIN*HDD

// -------- scratch (static device globals; no runtime alloc allowed) --------
__device__ float g_xt[NB * NHW * NHW * NC];            // x transposed to (b,y,x,c)
__device__ __nv_bfloat16 g_ahi[(size_t)MPAD * KD];     // sampled features hi (bf16)
__device__ __nv_bfloat16 g_alo[(size_t)MPAD * KD];     // sampled features lo (bf16)
__device__ uint4 g_bfrag[96 * 16 * 32];                // w_qkv in MMA-fragment order
__device__ uint2 g_qhl[(size_t)MPAD * NOUT3 / 2];      // qkv: per col-pair {hi2, lo2}
__device__ float g_o[(size_t)NB * OB_PER_B];           // attention out (scrambled-flat layout)
__device__ float g_ypre[NB * NWIN * NC];               // conv-reduced
__device__ float g_wpT[NC * NC];                       // w_proj transposed

// ======================= mma.sync / cp.async helpers (baseline ISA) =======================
__device__ __forceinline__ uint32_t smem_u32(const void* p) {
    uint32_t a;
    asm("{ .reg .u64 t; cvta.to.shared.u64 t, %1; cvt.u32.u64 %0, t; }" : "=r"(a) : "l"(p));
    return a;
}
__device__ __forceinline__ void ldsm_x4(uint32_t* r, uint32_t addr) {
    asm volatile("ldmatrix.sync.aligned.m8n8.x4.shared.b16 {%0,%1,%2,%3}, [%4];"
                 : "=r"(r[0]), "=r"(r[1]), "=r"(r[2]), "=r"(r[3]) : "r"(addr));
}
__device__ __forceinline__ void mma16816(float* c, const uint32_t* a, const uint32_t* b) {
    asm volatile("mma.sync.aligned.m16n8k16.row.col.f32.bf16.bf16.f32 "
                 "{%0,%1,%2,%3}, {%4,%5,%6,%7}, {%8,%9}, {%0,%1,%2,%3};"
                 : "+f"(c[0]), "+f"(c[1]), "+f"(c[2]), "+f"(c[3])
                 : "r"(a[0]), "r"(a[1]), "r"(a[2]), "r"(a[3]), "r"(b[0]), "r"(b[1]));
}
__device__ __forceinline__ void cp_async16(uint32_t saddr, const void* gptr) {
    asm volatile("cp.async.cg.shared.global [%0], [%1], 16;" :: "r"(saddr), "l"(gptr));
}
#define CP_COMMIT() asm volatile("cp.async.commit_group;" ::: "memory")
#define CP_WAIT1() asm volatile("cp.async.wait_group 1;" ::: "memory")
#define CP_WAIT0() asm volatile("cp.async.wait_group 0;" ::: "memory")

__device__ __forceinline__ uint32_t pack_bf2_hi(float a, float b) {
    __nv_bfloat162 t; t.x = __float2bfloat16(a); t.y = __float2bfloat16(b);
    return *(uint32_t*)&t;
}
__device__ __forceinline__ uint32_t pack_bf2_lo(float a, float b) {
    float ra = a - __bfloat162float(__float2bfloat16(a));
    float rb = b - __bfloat162float(__float2bfloat16(b));
    __nv_bfloat162 t; t.x = __float2bfloat16(ra); t.y = __float2bfloat16(rb);
    return *(uint32_t*)&t;
}

// -------- K0: x (B,C,H,W) -> xt (B,H,W,C), tiled transpose --------
__global__ void k_transpose_x(const float* __restrict__ x) {
    __shared__ float tile[32][33];
    int b = blockIdx.z;
    int c0 = blockIdx.y * 32, p0 = blockIdx.x * 32;
    #pragma unroll
    for (int i = threadIdx.y; i < 32; i += 8)
        tile[i][threadIdx.x] = x[((size_t)(b * NC + c0 + i) << 12) + p0 + threadIdx.x];
    __syncthreads();
    #pragma unroll
    for (int i = threadIdx.y; i < 32; i += 8)
        g_xt[(((size_t)b << 12) + p0 + i) * NC + c0 + threadIdx.x] = tile[threadIdx.x][i];
}

// -------- K1: poly eval + bilinear sample -> Ahi/Alo[b,n,s,c] (bf16 split) --------
__global__ void k_sample(const float* __restrict__ polys) {
    int j = blockIdx.x;                                // 0..58799 = ((b*600+n)*49+s)
    int t = threadIdx.x;                               // 0..63, 4 channels each
    int b = j / (NWIN * WS2);
    int r = j - b * (NWIN * WS2);
    int n = r / WS2;
    int s = r - n * WS2;
    int q = n / NP;
    int nid = n - q * NP;
    int m = nid * WS2 + s;
    int w = m / NP;
    int p = m - w * NP;

    const float* pc = polys + ((size_t)(b * NQ + q) * 2) * NP;
    float a = (float)p * 0.2f;
    float py = pc[0];
    #pragma unroll
    for (int i = 1; i < NP; i++) py = py * a + pc[i];
    float px = pc[NP];
    #pragma unroll
    for (int i = 1; i < NP; i++) px = px * a + pc[NP + i];
    py = 2.f * py - 1.f;
    px = 2.f * px - 1.f;

    int wy = w / WSZ, wx = w - wy * WSZ;
    float dy = (-4.0f + (float)wy * (7.0f / 6.0f)) * (2.0f / 64.0f);
    float dx = (-4.0f + (float)wx * (7.0f / 6.0f)) * (2.0f / 64.0f);
    float gy = py + dy, gx = px + dx;

    float fx = (gy + 1.f) * 0.5f * 63.f;
    float fy = (gx + 1.f) * 0.5f * 63.f;
    float x0f = floorf(fx), y0f = floorf(fy);
    float wx1 = fx - x0f, wy1 = fy - y0f;

    float vx0 = (x0f >= 0.f && x0f <= 63.f) ? 1.f : 0.f;
    float vx1 = (x0f + 1.f >= 0.f && x0f + 1.f <= 63.f) ? 1.f : 0.f;
    float vy0 = (y0f >= 0.f && y0f <= 63.f) ? 1.f : 0.f;
    float vy1 = (y0f + 1.f >= 0.f && y0f + 1.f <= 63.f) ? 1.f : 0.f;
    int xi0 = min(max((int)x0f, 0), 63);
    int xi1 = min(max((int)x0f + 1, 0), 63);
    int yi0 = min(max((int)y0f, 0), 63);
    int yi1 = min(max((int)y0f + 1, 0), 63);

    float w00 = (1.f - wy1) * (1.f - wx1) * vy0 * vx0;
    float w01 = (1.f - wy1) * wx1 * vy0 * vx1;
    float w10 = wy1 * (1.f - wx1) * vy1 * vx0;
    float w11 = wy1 * wx1 * vy1 * vx1;

    const float4* xt4 = (const float4*)g_xt;
    size_t pbase = (size_t)b * 4096;
    const float4* p00 = xt4 + (pbase + yi0 * 64 + xi0) * 64;
    const float4* p01 = xt4 + (pbase + yi0 * 64 + xi1) * 64;
    const float4* p10 = xt4 + (pbase + yi1 * 64 + xi0) * 64;
    const float4* p11 = xt4 + (pbase + yi1 * 64 + xi1) * 64;
    float4 v00 = p00[t], v01 = p01[t], v10 = p10[t], v11 = p11[t];
    float4 o;
    o.x = w00 * v00.x + w01 * v01.x + w10 * v10.x + w11 * v11.x;
    o.y = w00 * v00.y + w01 * v01.y + w10 * v10.y + w11 * v11.y;
    o.z = w00 * v00.z + w01 * v01.z + w10 * v10.z + w11 * v11.z;
    o.w = w00 * v00.w + w01 * v01.w + w10 * v10.w + w11 * v11.w;

    uint2 hv, lv;
    hv.x = pack_bf2_hi(o.x, o.y); hv.y = pack_bf2_hi(o.z, o.w);
    lv.x = pack_bf2_lo(o.x, o.y); lv.y = pack_bf2_lo(o.z, o.w);
    size_t base2 = (size_t)j * 64 + t;                 // uint2 units
    ((uint2*)g_ahi)[base2] = hv;
    ((uint2*)g_alo)[base2] = lv;
}

// -------- K1b: w_qkv -> per-lane MMA B-fragments (hi/lo packed in one uint4) --------
__global__ void k_wfrag(const float* __restrict__ wq) {
    int i = blockIdx.x * 256 + threadIdx.x;            // < 49152
    int lane = i & 31;
    int kt = (i >> 5) & 15;
    int nt = i >> 9;
    int n = nt * 8 + (lane >> 2);
    int kb = kt * 16 + (lane & 3) * 2;
    const float* row = wq + (size_t)n * KD;
    float v00 = row[kb],     v01 = row[kb + 1];
    float v10 = row[kb + 8], v11 = row[kb + 9];
    uint4 bf;
    bf.x = pack_bf2_hi(v00, v01);
    bf.y = pack_bf2_hi(v10, v11);
    bf.z = pack_bf2_lo(v00, v01);
    bf.w = pack_bf2_lo(v10, v11);
    g_bfrag[i] = bf;
}

// -------- K2: HMMA GEMM, A via cp.async smem (K-chunk 64), B via fragment LDG --------
#define SROWB 144                   // smem row stride bytes (64 bf16 data + 16B pad)
#define ARR2_B (128 * SROWB)        // 18432 B per array
#define STAGE2_B (2 * ARR2_B)       // 36864 B per stage (A hi + A lo)
#define GSM_TOTAL (2 * STAGE2_B)    // 73728 B

__global__ void __launch_bounds__(256, 2) k_gemm_mma(const float* __restrict__ bq) {
    extern __shared__ __align__(16) char dsm[];
    int tid = threadIdx.x;
    int wid = tid >> 5, lid = tid & 31;
    int wm = wid >> 1, wn = wid & 1;                   // 4 x 2 warp grid
    int bm = blockIdx.x * 128, bn = blockIdx.y * 128;

    float acc[2][8][4];
    #pragma unroll
    for (int t = 0; t < 2; t++)
        #pragma unroll
        for (int j = 0; j < 8; j++)
            #pragma unroll
            for (int e = 0; e < 4; e++) acc[t][j][e] = 0.f;

    uint32_t sbase = smem_u32(dsm);

    const char* GAh = (const char*)g_ahi;
    const char* GAl = (const char*)g_alo;
    const uint4* BF = (const uint4*)g_bfrag;
    int wb = ((bn + wn * 64) >> 3) * 512 + lid;

    int arow = lid & 15;
    int acolb = (lid >> 4) * 16;
    uint32_t aA0 = (uint32_t)((wm * 32 + arow) * SROWB) + acolb;

    // stage loader: 1024 16B-chunks per array (128 rows x 8), 4 chunks/thread/array
    auto load_stage = [&](int kc, int st) {
        uint32_t sb = sbase + st * STAGE2_B;
        #pragma unroll
        for (int i = tid; i < 1024; i += 256) {
            int row = i >> 3, u = i & 7;
            uint32_t so = (uint32_t)(row * SROWB) + u * 16;
            size_t ga = (size_t)(bm + row) * 512 + kc * 128 + u * 16;
            cp_async16(sb + so,          GAh + ga);
            cp_async16(sb + ARR2_B + so, GAl + ga);
        }
    };

    load_stage(0, 0);
    CP_COMMIT();

    for (int kc = 0; kc < 4; kc++) {
        int st = kc & 1;
        if (kc < 3) {
            load_stage(kc + 1, st ^ 1);
            CP_COMMIT();
            CP_WAIT1();
        } else {
            CP_WAIT0();
        }
        __syncthreads();

        uint32_t uAh = sbase + st * STAGE2_B;
        uint32_t uAl = uAh + ARR2_B;
        #pragma unroll
        for (int ks = 0; ks < 4; ks++) {
            int ktoff = (kc * 4 + ks) * 32;
            uint32_t ah[2][4], al[2][4];
            ldsm_x4(ah[0], uAh + aA0 + ks * 32);
            ldsm_x4(ah[1], uAh + aA0 + 16 * SROWB + ks * 32);
            ldsm_x4(al[0], uAl + aA0 + ks * 32);
            ldsm_x4(al[1], uAl + aA0 + 16 * SROWB + ks * 32);
            uint4 b0 = BF[wb + 0 * 512 + ktoff];
            uint4 b1 = BF[wb + 1 * 512 + ktoff];
            #pragma unroll
            for (int jp = 0; jp < 4; jp++) {
                uint4 n0, n1;
                if (jp < 3) {
                    n0 = BF[wb + (jp * 2 + 2) * 512 + ktoff];
                    n1 = BF[wb + (jp * 2 + 3) * 512 + ktoff];
                }
                int ja = jp * 2, jb = ja + 1;
                const uint32_t* p0 = (const uint32_t*)&b0;
                const uint32_t* p1 = (const uint32_t*)&b1;
                mma16816(acc[0][ja], ah[0], p0);
                mma16816(acc[0][jb], ah[0], p1);
                mma16816(acc[1][ja], ah[1], p0);
                mma16816(acc[1][jb], ah[1], p1);
                mma16816(acc[0][ja], ah[0], p0 + 2);
                mma16816(acc[0][jb], ah[0], p1 + 2);
                mma16816(acc[1][ja], ah[1], p0 + 2);
                mma16816(acc[1][jb], ah[1], p1 + 2);
                mma16816(acc[0][ja], al[0], p0);
                mma16816(acc[0][jb], al[0], p1);
                mma16816(acc[1][ja], al[1], p0);
                mma16816(acc[1][jb], al[1], p1);
                b0 = n0; b1 = n1;
            }
        }
        __syncthreads();
    }

    // epilogue: c-frag + bias -> interleaved uint2 {hi2, lo2} per col-pair
    int crow0 = bm + wm * 32 + (lid >> 2);
    int ccol0 = bn + wn * 64 + (lid & 3) * 2;
    #pragma unroll
    for (int t = 0; t < 2; t++) {
        #pragma unroll
        for (int j = 0; j < 8; j++) {
            int col = ccol0 + j * 8;
            float b0 = __ldg(&bq[col]);
            float b1 = __ldg(&bq[col + 1]);
            int row = crow0 + t * 16;
            float v00 = acc[t][j][0] + b0, v01 = acc[t][j][1] + b1;
            float v10 = acc[t][j][2] + b0, v11 = acc[t][j][3] + b1;
            uint2 s0, s1;
            s0.x = pack_bf2_hi(v00, v01); s0.y = pack_bf2_lo(v00, v01);
            s1.x = pack_bf2_hi(v10, v11); s1.y = pack_bf2_lo(v10, v11);
            g_qhl[((size_t)row * NOUT3 + col) >> 1] = s0;
            g_qhl[((size_t)(row + 8) * NOUT3 + col) >> 1] = s1;
        }
    }
}

// -------- K3: HMMA windowed attention, one (b,h,n) per block, 128 threads --------
#define ATT_QH 0            // 64 x 80B  (later PH: 64 x 144B)
#define ATT_QL 5120
#define ATT_KH 10240        // (later PL)
#define ATT_KL 15360
#define ATT_VTH 20480       // 32 x 144B
#define ATT_VTL 25088
#define ATT_S 29696         // 64 x 68 floats = 17408 (reused as O: 64 x 36 floats)
#define ATT_PH 0
#define ATT_PL 10240
#define ATT_SM 47104
#define SSTR 68

__global__ void __launch_bounds__(128) k_attn_mma(const float* __restrict__ pos_bias) {
    extern __shared__ __align__(16) char sma[];
    int tid = threadIdx.x;
    int wid = tid >> 5, lid = tid & 31;
    int blk = blockIdx.x;
    int b = blk / (NHD * NWIN);
    int r = blk - b * NHD * NWIN;
    int h = r / NWIN;
    int n = r - h * NWIN;
    uint32_t sb = smem_u32(sma);

    // 1. zero q/k/vT regions
    {
        uint4 z = make_uint4(0, 0, 0, 0);
        for (int i = tid; i < 1856; i += 128) *(uint4*)(sma + i * 16) = z;
    }
    __syncthreads();

    // 2. fill q/k (rows<49) and transposed v from interleaved g_qhl
    const uint4* GQ = (const uint4*)g_qhl;             // 1 uint4 = 4 cols {hi2,lo2}x2
    int grow0 = (b * NWIN + n) * WS2;
    for (int idx = tid; idx < 392; idx += 128) {       // q+k: 49 rows x 8 colgroups
        int row = idx >> 3, cg = idx & 7;              // cg: 4-col group within 32
        size_t base = (size_t)(grow0 + row) * 192 + h * 8 + cg;
        uint4 vq = GQ[base];                           // q cols h*32 + cg*4
        uint4 vk = GQ[base + 64];                      // k cols 256 + ...
        uint2 qh; qh.x = vq.x; qh.y = vq.z;
        uint2 ql; ql.x = vq.y; ql.y = vq.w;
        uint2 kh; kh.x = vk.x; kh.y = vk.z;
        uint2 kl; kl.x = vk.y; kl.y = vk.w;
        *(uint2*)(sma + ATT_QH + row * 80 + cg * 8) = qh;
        *(uint2*)(sma + ATT_QL + row * 80 + cg * 8) = ql;
        *(uint2*)(sma + ATT_KH + row * 80 + cg * 8) = kh;
        *(uint2*)(sma + ATT_KL + row * 80 + cg * 8) = kl;
    }
    for (int idx = tid; idx < 784; idx += 128) {       // vT: [d=32][c=64 pad]
        int c = idx >> 4, u = idx & 15;                // u = d-pair
        uint2 w = ((const uint2*)g_qhl)[(size_t)(grow0 + c) * 384 + 256 + h * 16 + u];
        __nv_bfloat162 vh2 = *(__nv_bfloat162*)&w.x;
        __nv_bfloat162 vl2 = *(__nv_bfloat162*)&w.y;
        __nv_bfloat16* th = (__nv_bfloat16*)(sma + ATT_VTH);
        __nv_bfloat16* tl = (__nv_bfloat16*)(sma + ATT_VTL);
        th[(2 * u) * 72 + c] = vh2.x; th[(2 * u + 1) * 72 + c] = vh2.y;
        tl[(2 * u) * 72 + c] = vl2.x; tl[(2 * u + 1) * 72 + c] = vl2.y;
    }
    __syncthreads();

    // 3. S = q k^T via HMMA (3-term hi/lo)
    {
        float accs[8][4];
        #pragma unroll
        for (int j = 0; j < 8; j++)
            #pragma unroll
            for (int e = 0; e < 4; e++) accs[j][e] = 0.f;
        int arow = lid & 15, acolb = (lid >> 4) * 16;
        int brow = ((lid >> 4) & 1) * 8 + (lid & 7);
        int bcolb = ((lid >> 3) & 1) * 16;
        uint32_t aQh = sb + ATT_QH + (wid * 16 + arow) * 80 + acolb;
        uint32_t aQl = sb + ATT_QL + (wid * 16 + arow) * 80 + acolb;
        uint32_t aKh = sb + ATT_KH + brow * 80 + bcolb;
        uint32_t aKl = sb + ATT_KL + brow * 80 + bcolb;
        #pragma unroll
        for (int ks = 0; ks < 2; ks++) {
            uint32_t ah[4], al[4];
            ldsm_x4(ah, aQh + ks * 32);
            ldsm_x4(al, aQl + ks * 32);
            #pragma unroll
            for (int g = 0; g < 4; g++) {
                uint32_t bh[4], bl[4];
                ldsm_x4(bh, aKh + g * 16 * 80 + ks * 32);
                ldsm_x4(bl, aKl + g * 16 * 80 + ks * 32);
                mma16816(accs[g * 2],     ah, bh);
                mma16816(accs[g * 2 + 1], ah, bh + 2);
                mma16816(accs[g * 2],     ah, bl);
                mma16816(accs[g * 2 + 1], ah, bl + 2);
                mma16816(accs[g * 2],     al, bh);
                mma16816(accs[g * 2 + 1], al, bh + 2);
            }
        }
        float* S = (float*)(sma + ATT_S);
        int srow = wid * 16 + (lid >> 2), scol = (lid & 3) * 2;
        #pragma unroll
        for (int j = 0; j < 8; j++) {
            *(float2*)&S[srow * SSTR + j * 8 + scol]       = make_float2(accs[j][0], accs[j][1]);
            *(float2*)&S[(srow + 8) * SSTR + j * 8 + scol] = make_float2(accs[j][2], accs[j][3]);
        }
    }
    __syncthreads();

    // 4. zero P regions (overlays dead q/k)
    {
        uint4 z = make_uint4(0, 0, 0, 0);
        for (int i = tid; i < 1280; i += 128) *(uint4*)(sma + i * 16) = z;
    }
    __syncthreads();

    // 5. fp32 softmax per row p (<49), write P as bf16 hi/lo
    if (tid < WS2) {
        float* S = (float*)(sma + ATT_S) + tid * SSTR;
        const float scale = 0.17677669529663687f;
        float pb = pos_bias[tid];
        float mx = -1e30f;
        #pragma unroll 7
        for (int c = 0; c < WS2; c++) { float v = S[c] * scale + pb; S[c] = v; mx = fmaxf(mx, v); }
        float sum = 0.f;
        #pragma unroll 7
        for (int c = 0; c < WS2; c++) { float e = __expf(S[c] - mx); S[c] = e; sum += e; }
        float inv = 1.f / sum;
        __nv_bfloat16* PH = (__nv_bfloat16*)(sma + ATT_PH) + tid * 72;
        __nv_bfloat16* PL = (__nv_bfloat16*)(sma + ATT_PL) + tid * 72;
        #pragma unroll 7
        for (int c = 0; c < WS2; c++) {
            float p = S[c] * inv;
            __nv_bfloat16 hi = __float2bfloat16(p);
            PH[c] = hi;
            PL[c] = __float2bfloat16(p - __bfloat162float(hi));
        }
    }
    __syncthreads();

    // 6. O = P V via HMMA (3-term)
    {
        float acco[4][4];
        #pragma unroll
        for (int j = 0; j < 4; j++)
            #pragma unroll
            for (int e = 0; e < 4; e++) acco[j][e] = 0.f;
        int arow = lid & 15, acolb = (lid >> 4) * 16;
        int brow = ((lid >> 4) & 1) * 8 + (lid & 7);
        int bcolb = ((lid >> 3) & 1) * 16;
        uint32_t aPh = sb + ATT_PH + (wid * 16 + arow) * 144 + acolb;
        uint32_t aPl = sb + ATT_PL + (wid * 16 + arow) * 144 + acolb;
        uint32_t aVh = sb + ATT_VTH + brow * 144 + bcolb;
        uint32_t aVl = sb + ATT_VTL + brow * 144 + bcolb;
        #pragma unroll
        for (int ks = 0; ks < 4; ks++) {
            uint32_t ph[4], pl[4];
            ldsm_x4(ph, aPh + ks * 32);
            ldsm_x4(pl, aPl + ks * 32);
            #pragma unroll
            for (int g = 0; g < 2; g++) {
                uint32_t vh[4], vl[4];
                ldsm_x4(vh, aVh + g * 16 * 144 + ks * 32);
                ldsm_x4(vl, aVl + g * 16 * 144 + ks * 32);
                mma16816(acco[g * 2],     ph, vh);
                mma16816(acco[g * 2 + 1], ph, vh + 2);
                mma16816(acco[g * 2],     ph, vl);
                mma16816(acco[g * 2 + 1], ph, vl + 2);
                mma16816(acco[g * 2],     pl, vh);
                mma16816(acco[g * 2 + 1], pl, vh + 2);
            }
        }
        float* O = (float*)(sma + ATT_S);
        int orow = wid * 16 + (lid >> 2), ocol = (lid & 3) * 2;
        #pragma unroll
        for (int j = 0; j < 4; j++) {
            *(float2*)&O[orow * 36 + j * 8 + ocol]       = make_float2(acco[j][0], acco[j][1]);
            *(float2*)&O[(orow + 8) * 36 + j * 8 + ocol] = make_float2(acco[j][2], acco[j][3]);
        }
    }
    __syncthreads();

    // 7. store o[p<49][d<32] to scrambled-flat g_o
    size_t obase = (size_t)b * OB_PER_B + (size_t)h * (WS2 * NWIN * HDD) + (size_t)n * HDD;
    const float* O = (const float*)(sma + ATT_S);
    for (int idx = tid; idx < WS2 * 8; idx += 128) {
        int p = idx >> 3, d4 = (idx & 7) * 4;
        float4 v = *(const float4*)&O[p * 36 + d4];
        *(float4*)&g_o[obase + (size_t)p * (NWIN * HDD) + d4] = v;
    }
}

// -------- K4: conv reduce over scrambled s2 axis --------
__global__ void k_conv(const float* __restrict__ conv_w, const float* __restrict__ conv_b) {
    __shared__ float cw[WS2];
    int tid = threadIdx.x;
    if (tid < WS2) cw[tid] = conv_w[tid];
    __syncthreads();
    int idx = blockIdx.x * 256 + tid;                  // < 307200
    int b = idx / (NWIN * NC);
    int r = idx - b * (NWIN * NC);
    int n2 = r >> 8, c2 = r & 255;
    size_t base = (size_t)b * OB_PER_B + (size_t)n2 * (WS2 * NC) + c2;
    float accv = conv_b[0];
    #pragma unroll 7
    for (int s2 = 0; s2 < WS2; s2++) accv += cw[s2] * g_o[base + (size_t)s2 * NC];
    g_ypre[idx] = accv;
}

// -------- K5a: transpose w_proj --------
__global__ void k_wpt(const float* __restrict__ wp) {
    int idx = blockIdx.x * 256 + threadIdx.x;          // < 65536
    int k = idx >> 8, c = idx & 255;
    g_wpT[idx] = wp[c * NC + k];
}

// -------- K5b: y = ypre @ w_proj^T + b_proj (4 rows/block) --------
__global__ void __launch_bounds__(256) k_proj(const float* __restrict__ bp, float* __restrict__ out) {
    __shared__ float rowv[4][NC];
    int row0 = blockIdx.x * 4;
    int c = threadIdx.x;
    #pragma unroll
    for (int i = 0; i < 4; i++) rowv[i][c] = g_ypre[(size_t)(row0 + i) * NC + c];
    __syncthreads();
    float a0 = 0.f, a1 = 0.f, a2 = 0.f, a3 = 0.f;
    #pragma unroll 8
    for (int k = 0; k < NC; k++) {
        float wv = g_wpT[k * NC + c];
        a0 += rowv[0][k] * wv; a1 += rowv[1][k] * wv;
        a2 += rowv[2][k] * wv; a3 += rowv[3][k] * wv;
    }
    float bb = bp[c];
    out[(size_t)(row0 + 0) * NC + c] = a0 + bb;
    out[(size_t)(row0 + 1) * NC + c] = a1 + bb;
    out[(size_t)(row0 + 2) * NC + c] = a2 + bb;
    out[(size_t)(row0 + 3) * NC + c] = a3 + bb;
}

extern "C" void kernel_launch(void* const* d_in, const int* in_sizes, int n_in,
                              void* d_out, int out_size) {
    const float* x        = (const float*)d_in[0];
    const float* polys    = (const float*)d_in[1];
    const float* w_qkv    = (const float*)d_in[2];
    const float* b_qkv    = (const float*)d_in[3];
    const float* w_proj   = (const float*)d_in[4];
    const float* b_proj   = (const float*)d_in[5];
    const float* conv_w   = (const float*)d_in[6];
    const float* conv_b   = (const float*)d_in[7];
    const float* pos_bias = (const float*)d_in[8];
    float* out = (float*)d_out;

    static int smem_set = 0;
    if (!smem_set) {
        cudaFuncSetAttribute(k_gemm_mma, cudaFuncAttributeMaxDynamicSharedMemorySize, GSM_TOTAL);
        cudaFuncSetAttribute(k_attn_mma, cudaFuncAttributeMaxDynamicSharedMemorySize, ATT_SM);
        smem_set = 1;
    }

    dim3 gt(128, 8, 2);
    dim3 bt(32, 8);
    k_transpose_x<<<gt, bt>>>(x);
    k_sample<<<NROWS, 64>>>(polys);
    k_wfrag<<<(96 * 16 * 32) / 256, 256>>>(w_qkv);
    dim3 g2(MPAD / 128, NOUT3 / 128);
    k_gemm_mma<<<g2, 256, GSM_TOTAL>>>(b_qkv);
    k_attn_mma<<<NB * NHD * NWIN, 128, ATT_SM>>>(pos_bias);
    k_conv<<<(NB * NWIN * NC) / 256, 256>>>(conv_w, conv_b);
    k_wpt<<<NC * NC / 256, 256>>>(w_proj);
    k_proj<<<NB * NWIN / 4, 256>>>(b_proj, out);
}

// round 14
// speedup vs baseline: 2.1233x; 1.1600x over previous
#include <cuda_runtime.h>
#include <cuda_bf16.h>
#include <cstdint>
#include <math.h>

#define NB 2
#define NQ 100
#define NC 256
#define NHW 64
#define NP 6
#define WSZ 7
#define WS2 49
#define NHD 8
#define HDD 32
#define NWIN 600            // Q*NP
#define NROWS 58800         // NB*NWIN*WS2
#define MPAD 58880          // 460*128 (GEMM M padding)
#define KD 256
#define NOUT3 768
#define OB_PER_B 7526400    // NHD*WS2*NWIN*HDD

// -------- scratch (static device globals; no runtime alloc allowed) --------
__device__ float g_xt[NB * NHW * NHW * NC];            // x transposed to (b,y,x,c)
__device__ __nv_bfloat16 g_ahi[(size_t)MPAD * KD];     // sampled features hi (bf16)
__device__ __nv_bfloat16 g_alo[(size_t)MPAD * KD];     // sampled features lo (bf16)
__device__ uint4 g_bfrag[96 * 16 * 32];                // w_qkv in MMA-fragment order
__device__ uint2 g_qhl[(size_t)MPAD * NOUT3 / 2];      // qkv: per col-pair {hi2, lo2}
__device__ float g_o[(size_t)NB * OB_PER_B];           // attention out (scrambled-flat layout)
__device__ float g_ypre[NB * NWIN * NC];               // conv-reduced
__device__ float g_wpT[NC * NC];                       // w_proj transposed

// ======================= mma.sync / cp.async helpers (baseline ISA) =======================
__device__ __forceinline__ uint32_t smem_u32(const void* p) {
    uint32_t a;
    asm("{ .reg .u64 t; cvta.to.shared.u64 t, %1; cvt.u32.u64 %0, t; }" : "=r"(a) : "l"(p));
    return a;
}
__device__ __forceinline__ void ldsm_x4(uint32_t* r, uint32_t addr) {
    asm volatile("ldmatrix.sync.aligned.m8n8.x4.shared.b16 {%0,%1,%2,%3}, [%4];"
                 : "=r"(r[0]), "=r"(r[1]), "=r"(r[2]), "=r"(r[3]) : "r"(addr));
}
__device__ __forceinline__ void mma16816(float* c, const uint32_t* a, const uint32_t* b) {
    asm volatile("mma.sync.aligned.m16n8k16.row.col.f32.bf16.bf16.f32 "
                 "{%0,%1,%2,%3}, {%4,%5,%6,%7}, {%8,%9}, {%0,%1,%2,%3};"
                 : "+f"(c[0]), "+f"(c[1]), "+f"(c[2]), "+f"(c[3])
                 : "r"(a[0]), "r"(a[1]), "r"(a[2]), "r"(a[3]), "r"(b[0]), "r"(b[1]));
}
__device__ __forceinline__ void cp_async16(uint32_t saddr, const void* gptr) {
    asm volatile("cp.async.cg.shared.global [%0], [%1], 16;" :: "r"(saddr), "l"(gptr));
}
#define CP_COMMIT() asm volatile("cp.async.commit_group;" ::: "memory")
#define CP_WAIT1() asm volatile("cp.async.wait_group 1;" ::: "memory")
#define CP_WAIT0() asm volatile("cp.async.wait_group 0;" ::: "memory")

__device__ __forceinline__ uint32_t pack_bf2_hi(float a, float b) {
    __nv_bfloat162 t; t.x = __float2bfloat16(a); t.y = __float2bfloat16(b);
    return *(uint32_t*)&t;
}
__device__ __forceinline__ uint32_t pack_bf2_lo(float a, float b) {
    float ra = a - __bfloat162float(__float2bfloat16(a));
    float rb = b - __bfloat162float(__float2bfloat16(b));
    __nv_bfloat162 t; t.x = __float2bfloat16(ra); t.y = __float2bfloat16(rb);
    return *(uint32_t*)&t;
}

// -------- K0: x (B,C,H,W) -> xt (B,H,W,C), tiled transpose --------
__global__ void k_transpose_x(const float* __restrict__ x) {
    __shared__ float tile[32][33];
    int b = blockIdx.z;
    int c0 = blockIdx.y * 32, p0 = blockIdx.x * 32;
    #pragma unroll
    for (int i = threadIdx.y; i < 32; i += 8)
        tile[i][threadIdx.x] = x[((size_t)(b * NC + c0 + i) << 12) + p0 + threadIdx.x];
    __syncthreads();
    #pragma unroll
    for (int i = threadIdx.y; i < 32; i += 8)
        g_xt[(((size_t)b << 12) + p0 + i) * NC + c0 + threadIdx.x] = tile[threadIdx.x][i];
}

// -------- K1: poly eval + bilinear sample -> Ahi/Alo[b,n,s,c] (bf16 split) --------
__global__ void k_sample(const float* __restrict__ polys) {
    int j = blockIdx.x;                                // 0..58799 = ((b*600+n)*49+s)
    int t = threadIdx.x;                               // 0..63, 4 channels each
    int b = j / (NWIN * WS2);
    int r = j - b * (NWIN * WS2);
    int n = r / WS2;
    int s = r - n * WS2;
    int q = n / NP;
    int nid = n - q * NP;
    int m = nid * WS2 + s;
    int w = m / NP;
    int p = m - w * NP;

    const float* pc = polys + ((size_t)(b * NQ + q) * 2) * NP;
    float a = (float)p * 0.2f;
    float py = pc[0];
    #pragma unroll
    for (int i = 1; i < NP; i++) py = py * a + pc[i];
    float px = pc[NP];
    #pragma unroll
    for (int i = 1; i < NP; i++) px = px * a + pc[NP + i];
    py = 2.f * py - 1.f;
    px = 2.f * px - 1.f;

    int wy = w / WSZ, wx = w - wy * WSZ;
    float dy = (-4.0f + (float)wy * (7.0f / 6.0f)) * (2.0f / 64.0f);
    float dx = (-4.0f + (float)wx * (7.0f / 6.0f)) * (2.0f / 64.0f);
    float gy = py + dy, gx = px + dx;

    float fx = (gy + 1.f) * 0.5f * 63.f;
    float fy = (gx + 1.f) * 0.5f * 63.f;
    float x0f = floorf(fx), y0f = floorf(fy);
    float wx1 = fx - x0f, wy1 = fy - y0f;

    float vx0 = (x0f >= 0.f && x0f <= 63.f) ? 1.f : 0.f;
    float vx1 = (x0f + 1.f >= 0.f && x0f + 1.f <= 63.f) ? 1.f : 0.f;
    float vy0 = (y0f >= 0.f && y0f <= 63.f) ? 1.f : 0.f;
    float vy1 = (y0f + 1.f >= 0.f && y0f + 1.f <= 63.f) ? 1.f : 0.f;
    int xi0 = min(max((int)x0f, 0), 63);
    int xi1 = min(max((int)x0f + 1, 0), 63);
    int yi0 = min(max((int)y0f, 0), 63);
    int yi1 = min(max((int)y0f + 1, 0), 63);

    float w00 = (1.f - wy1) * (1.f - wx1) * vy0 * vx0;
    float w01 = (1.f - wy1) * wx1 * vy0 * vx1;
    float w10 = wy1 * (1.f - wx1) * vy1 * vx0;
    float w11 = wy1 * wx1 * vy1 * vx1;

    const float4* xt4 = (const float4*)g_xt;
    size_t pbase = (size_t)b * 4096;
    const float4* p00 = xt4 + (pbase + yi0 * 64 + xi0) * 64;
    const float4* p01 = xt4 + (pbase + yi0 * 64 + xi1) * 64;
    const float4* p10 = xt4 + (pbase + yi1 * 64 + xi0) * 64;
    const float4* p11 = xt4 + (pbase + yi1 * 64 + xi1) * 64;
    float4 v00 = p00[t], v01 = p01[t], v10 = p10[t], v11 = p11[t];
    float4 o;
    o.x = w00 * v00.x + w01 * v01.x + w10 * v10.x + w11 * v11.x;
    o.y = w00 * v00.y + w01 * v01.y + w10 * v10.y + w11 * v11.y;
    o.z = w00 * v00.z + w01 * v01.z + w10 * v10.z + w11 * v11.z;
    o.w = w00 * v00.w + w01 * v01.w + w10 * v10.w + w11 * v11.w;

    uint2 hv, lv;
    hv.x = pack_bf2_hi(o.x, o.y); hv.y = pack_bf2_hi(o.z, o.w);
    lv.x = pack_bf2_lo(o.x, o.y); lv.y = pack_bf2_lo(o.z, o.w);
    size_t base2 = (size_t)j * 64 + t;                 // uint2 units
    ((uint2*)g_ahi)[base2] = hv;
    ((uint2*)g_alo)[base2] = lv;
}

// -------- K1b: w_qkv -> per-lane MMA B-fragments (hi/lo packed in one uint4) --------
__global__ void k_wfrag(const float* __restrict__ wq) {
    int i = blockIdx.x * 256 + threadIdx.x;            // < 49152
    int lane = i & 31;
    int kt = (i >> 5) & 15;
    int nt = i >> 9;
    int n = nt * 8 + (lane >> 2);
    int kb = kt * 16 + (lane & 3) * 2;
    const float* row = wq + (size_t)n * KD;
    float v00 = row[kb],     v01 = row[kb + 1];
    float v10 = row[kb + 8], v11 = row[kb + 9];
    uint4 bf;
    bf.x = pack_bf2_hi(v00, v01);
    bf.y = pack_bf2_hi(v10, v11);
    bf.z = pack_bf2_lo(v00, v01);
    bf.w = pack_bf2_lo(v10, v11);
    g_bfrag[i] = bf;
}

// -------- K2: HMMA GEMM, A via cp.async smem (K-chunk 64), B via fragment LDG --------
#define SROWB 144                   // smem row stride bytes (64 bf16 data + 16B pad)
#define ARR2_B (128 * SROWB)        // 18432 B per array
#define STAGE2_B (2 * ARR2_B)       // 36864 B per stage (A hi + A lo)
#define GSM_TOTAL (2 * STAGE2_B)    // 73728 B

__global__ void __launch_bounds__(256, 2) k_gemm_mma(const float* __restrict__ bq) {
    extern __shared__ __align__(16) char dsm[];
    int tid = threadIdx.x;
    int wid = tid >> 5, lid = tid & 31;
    int wm = wid >> 1, wn = wid & 1;                   // 4 x 2 warp grid
    int bm = blockIdx.x * 128, bn = blockIdx.y * 128;

    float acc[2][8][4];
    #pragma unroll
    for (int t = 0; t < 2; t++)
        #pragma unroll
        for (int j = 0; j < 8; j++)
            #pragma unroll
            for (int e = 0; e < 4; e++) acc[t][j][e] = 0.f;

    uint32_t sbase = smem_u32(dsm);

    const char* GAh = (const char*)g_ahi;
    const char* GAl = (const char*)g_alo;
    const uint4* BF = (const uint4*)g_bfrag;
    int wb = ((bn + wn * 64) >> 3) * 512 + lid;

    int arow = lid & 15;
    int acolb = (lid >> 4) * 16;
    uint32_t aA0 = (uint32_t)((wm * 32 + arow) * SROWB) + acolb;

    auto load_stage = [&](int kc, int st) {
        uint32_t sb = sbase + st * STAGE2_B;
        #pragma unroll
        for (int i = tid; i < 1024; i += 256) {
            int row = i >> 3, u = i & 7;
            uint32_t so = (uint32_t)(row * SROWB) + u * 16;
            size_t ga = (size_t)(bm + row) * 512 + kc * 128 + u * 16;
            cp_async16(sb + so,          GAh + ga);
            cp_async16(sb + ARR2_B + so, GAl + ga);
        }
    };

    load_stage(0, 0);
    CP_COMMIT();

    for (int kc = 0; kc < 4; kc++) {
        int st = kc & 1;
        if (kc < 3) {
            load_stage(kc + 1, st ^ 1);
            CP_COMMIT();
            CP_WAIT1();
        } else {
            CP_WAIT0();
        }
        __syncthreads();

        uint32_t uAh = sbase + st * STAGE2_B;
        uint32_t uAl = uAh + ARR2_B;
        #pragma unroll
        for (int ks = 0; ks < 4; ks++) {
            int ktoff = (kc * 4 + ks) * 32;
            uint32_t ah[2][4], al[2][4];
            ldsm_x4(ah[0], uAh + aA0 + ks * 32);
            ldsm_x4(ah[1], uAh + aA0 + 16 * SROWB + ks * 32);
            ldsm_x4(al[0], uAl + aA0 + ks * 32);
            ldsm_x4(al[1], uAl + aA0 + 16 * SROWB + ks * 32);
            uint4 b0 = BF[wb + 0 * 512 + ktoff];
            uint4 b1 = BF[wb + 1 * 512 + ktoff];
            #pragma unroll
            for (int jp = 0; jp < 4; jp++) {
                uint4 n0, n1;
                if (jp < 3) {
                    n0 = BF[wb + (jp * 2 + 2) * 512 + ktoff];
                    n1 = BF[wb + (jp * 2 + 3) * 512 + ktoff];
                }
                int ja = jp * 2, jb = ja + 1;
                const uint32_t* p0 = (const uint32_t*)&b0;
                const uint32_t* p1 = (const uint32_t*)&b1;
                mma16816(acc[0][ja], ah[0], p0);
                mma16816(acc[0][jb], ah[0], p1);
                mma16816(acc[1][ja], ah[1], p0);
                mma16816(acc[1][jb], ah[1], p1);
                mma16816(acc[0][ja], ah[0], p0 + 2);
                mma16816(acc[0][jb], ah[0], p1 + 2);
                mma16816(acc[1][ja], ah[1], p0 + 2);
                mma16816(acc[1][jb], ah[1], p1 + 2);
                mma16816(acc[0][ja], al[0], p0);
                mma16816(acc[0][jb], al[0], p1);
                mma16816(acc[1][ja], al[1], p0);
                mma16816(acc[1][jb], al[1], p1);
                b0 = n0; b1 = n1;
            }
        }
        __syncthreads();
    }

    // epilogue: c-frag + bias -> interleaved uint2 {hi2, lo2} per col-pair
    int crow0 = bm + wm * 32 + (lid >> 2);
    int ccol0 = bn + wn * 64 + (lid & 3) * 2;
    #pragma unroll
    for (int t = 0; t < 2; t++) {
        #pragma unroll
        for (int j = 0; j < 8; j++) {
            int col = ccol0 + j * 8;
            float b0 = __ldg(&bq[col]);
            float b1 = __ldg(&bq[col + 1]);
            int row = crow0 + t * 16;
            float v00 = acc[t][j][0] + b0, v01 = acc[t][j][1] + b1;
            float v10 = acc[t][j][2] + b0, v11 = acc[t][j][3] + b1;
            uint2 s0, s1;
            s0.x = pack_bf2_hi(v00, v01); s0.y = pack_bf2_lo(v00, v01);
            s1.x = pack_bf2_hi(v10, v11); s1.y = pack_bf2_lo(v10, v11);
            g_qhl[((size_t)row * NOUT3 + col) >> 1] = s0;
            g_qhl[((size_t)(row + 8) * NOUT3 + col) >> 1] = s1;
        }
    }
}

// -------- K3: HMMA windowed attention, one (b,h,n) per block, 128 threads --------
// Pad rows/cols of q/k/P left as garbage: they only propagate to S rows>=49,
// S cols>=52 (masked in softmax) and O rows>=49 (never stored). vT pad cols are
// zero-filled in the fill loop (needed: P=0 x V=NaN would poison O).
#define ATT_QH 0            // 64 x 80B  (later PH: 64 x 144B)
#define ATT_QL 5120
#define ATT_KH 10240        // (later PL)
#define ATT_KL 15360
#define ATT_VTH 20480       // 32 x 144B
#define ATT_VTL 25088
#define ATT_S 29696         // 64 x 68 floats = 17408 (reused as O: 64 x 36 floats)
#define ATT_PH 0
#define ATT_PL 10240
#define ATT_SM 47104
#define SSTR 68

__global__ void __launch_bounds__(128) k_attn_mma(const float* __restrict__ pos_bias) {
    extern __shared__ __align__(16) char sma[];
    int tid = threadIdx.x;
    int wid = tid >> 5, lid = tid & 31;
    int blk = blockIdx.x;
    int b = blk / (NHD * NWIN);
    int r = blk - b * NHD * NWIN;
    int h = r / NWIN;
    int n = r - h * NWIN;
    uint32_t sb = smem_u32(sma);

    // 1. fill q/k (rows<49) and transposed v (cols>=49 zeroed inline)
    const uint4* GQ = (const uint4*)g_qhl;             // 1 uint4 = 4 cols {hi2,lo2}x2
    int grow0 = (b * NWIN + n) * WS2;
    for (int idx = tid; idx < 392; idx += 128) {       // q+k: 49 rows x 8 colgroups
        int row = idx >> 3, cg = idx & 7;
        size_t base = (size_t)(grow0 + row) * 192 + h * 8 + cg;
        uint4 vq = GQ[base];
        uint4 vk = GQ[base + 64];
        uint2 qh; qh.x = vq.x; qh.y = vq.z;
        uint2 ql; ql.x = vq.y; ql.y = vq.w;
        uint2 kh; kh.x = vk.x; kh.y = vk.z;
        uint2 kl; kl.x = vk.y; kl.y = vk.w;
        *(uint2*)(sma + ATT_QH + row * 80 + cg * 8) = qh;
        *(uint2*)(sma + ATT_QL + row * 80 + cg * 8) = ql;
        *(uint2*)(sma + ATT_KH + row * 80 + cg * 8) = kh;
        *(uint2*)(sma + ATT_KL + row * 80 + cg * 8) = kl;
    }
    for (int idx = tid; idx < 1024; idx += 128) {      // vT: [d=32][c=64]
        int c = idx >> 4, u = idx & 15;                // u = d-pair
        uint2 w = make_uint2(0u, 0u);
        if (c < WS2)
            w = ((const uint2*)g_qhl)[(size_t)(grow0 + c) * 384 + 256 + h * 16 + u];
        __nv_bfloat162 vh2 = *(__nv_bfloat162*)&w.x;
        __nv_bfloat162 vl2 = *(__nv_bfloat162*)&w.y;
        __nv_bfloat16* th = (__nv_bfloat16*)(sma + ATT_VTH);
        __nv_bfloat16* tl = (__nv_bfloat16*)(sma + ATT_VTL);
        th[(2 * u) * 72 + c] = vh2.x; th[(2 * u + 1) * 72 + c] = vh2.y;
        tl[(2 * u) * 72 + c] = vl2.x; tl[(2 * u + 1) * 72 + c] = vl2.y;
    }
    __syncthreads();

    // 2. S = q k^T via HMMA (3-term hi/lo)
    {
        float accs[8][4];
        #pragma unroll
        for (int j = 0; j < 8; j++)
            #pragma unroll
            for (int e = 0; e < 4; e++) accs[j][e] = 0.f;
        int arow = lid & 15, acolb = (lid >> 4) * 16;
        int brow = ((lid >> 4) & 1) * 8 + (lid & 7);
        int bcolb = ((lid >> 3) & 1) * 16;
        uint32_t aQh = sb + ATT_QH + (wid * 16 + arow) * 80 + acolb;
        uint32_t aQl = sb + ATT_QL + (wid * 16 + arow) * 80 + acolb;
        uint32_t aKh = sb + ATT_KH + brow * 80 + bcolb;
        uint32_t aKl = sb + ATT_KL + brow * 80 + bcolb;
        #pragma unroll
        for (int ks = 0; ks < 2; ks++) {
            uint32_t ah[4], al[4];
            ldsm_x4(ah, aQh + ks * 32);
            ldsm_x4(al, aQl + ks * 32);
            #pragma unroll
            for (int g = 0; g < 4; g++) {
                uint32_t bh[4], bl[4];
                ldsm_x4(bh, aKh + g * 16 * 80 + ks * 32);
                ldsm_x4(bl, aKl + g * 16 * 80 + ks * 32);
                mma16816(accs[g * 2],     ah, bh);
                mma16816(accs[g * 2 + 1], ah, bh + 2);
                mma16816(accs[g * 2],     ah, bl);
                mma16816(accs[g * 2 + 1], ah, bl + 2);
                mma16816(accs[g * 2],     al, bh);
                mma16816(accs[g * 2 + 1], al, bh + 2);
            }
        }
        float* S = (float*)(sma + ATT_S);
        int srow = wid * 16 + (lid >> 2), scol = (lid & 3) * 2;
        #pragma unroll
        for (int j = 0; j < 8; j++) {
            *(float2*)&S[srow * SSTR + j * 8 + scol]       = make_float2(accs[j][0], accs[j][1]);
            *(float2*)&S[(srow + 8) * SSTR + j * 8 + scol] = make_float2(accs[j][2], accs[j][3]);
        }
    }
    __syncthreads();

    // 3. vectorized fp32 softmax per row (<49); write full 144B P rows (tails = 0)
    if (tid < WS2) {
        const float scale = 0.17677669529663687f;
        float pb = pos_bias[tid];
        const float4* S4 = (const float4*)(sma + ATT_S) + tid * (SSTR / 4);
        float4 rv[13];
        #pragma unroll
        for (int i = 0; i < 13; i++) rv[i] = S4[i];
        #pragma unroll
        for (int i = 0; i < 13; i++) {
            rv[i].x = rv[i].x * scale + pb; rv[i].y = rv[i].y * scale + pb;
            rv[i].z = rv[i].z * scale + pb; rv[i].w = rv[i].w * scale + pb;
        }
        float mx = rv[12].x;
        #pragma unroll
        for (int i = 0; i < 12; i++)
            mx = fmaxf(mx, fmaxf(fmaxf(rv[i].x, rv[i].y), fmaxf(rv[i].z, rv[i].w)));
        float sum = 0.f;
        #pragma unroll
        for (int i = 0; i < 12; i++) {
            rv[i].x = __expf(rv[i].x - mx); rv[i].y = __expf(rv[i].y - mx);
            rv[i].z = __expf(rv[i].z - mx); rv[i].w = __expf(rv[i].w - mx);
            sum += rv[i].x + rv[i].y + rv[i].z + rv[i].w;
        }
        rv[12].x = __expf(rv[12].x - mx);
        rv[12].y = 0.f; rv[12].z = 0.f; rv[12].w = 0.f;
        sum += rv[12].x;
        float inv = 1.f / sum;
        uint32_t* PH32 = (uint32_t*)(sma + ATT_PH) + tid * 36;
        uint32_t* PL32 = (uint32_t*)(sma + ATT_PL) + tid * 36;
        #pragma unroll
        for (int cp = 0; cp < 26; cp++) {
            float a  = ((cp & 1) ? rv[cp >> 1].z : rv[cp >> 1].x) * inv;
            float b2 = ((cp & 1) ? rv[cp >> 1].w : rv[cp >> 1].y) * inv;
            PH32[cp] = pack_bf2_hi(a, b2);
            PL32[cp] = pack_bf2_lo(a, b2);
        }
        #pragma unroll
        for (int cp = 26; cp < 36; cp++) { PH32[cp] = 0u; PL32[cp] = 0u; }
    }
    __syncthreads();

    // 4. O = P V via HMMA (3-term)
    {
        float acco[4][4];
        #pragma unroll
        for (int j = 0; j < 4; j++)
            #pragma unroll
            for (int e = 0; e < 4; e++) acco[j][e] = 0.f;
        int arow = lid & 15, acolb = (lid >> 4) * 16;
        int brow = ((lid >> 4) & 1) * 8 + (lid & 7);
        int bcolb = ((lid >> 3) & 1) * 16;
        uint32_t aPh = sb + ATT_PH + (wid * 16 + arow) * 144 + acolb;
        uint32_t aPl = sb + ATT_PL + (wid * 16 + arow) * 144 + acolb;
        uint32_t aVh = sb + ATT_VTH + brow * 144 + bcolb;
        uint32_t aVl = sb + ATT_VTL + brow * 144 + bcolb;
        #pragma unroll
        for (int ks = 0; ks < 4; ks++) {
            uint32_t ph[4], pl[4];
            ldsm_x4(ph, aPh + ks * 32);
            ldsm_x4(pl, aPl + ks * 32);
            #pragma unroll
            for (int g = 0; g < 2; g++) {
                uint32_t vh[4], vl[4];
                ldsm_x4(vh, aVh + g * 16 * 144 + ks * 32);
                ldsm_x4(vl, aVl + g * 16 * 144 + ks * 32);
                mma16816(acco[g * 2],     ph, vh);
                mma16816(acco[g * 2 + 1], ph, vh + 2);
                mma16816(acco[g * 2],     ph, vl);
                mma16816(acco[g * 2 + 1], ph, vl + 2);
                mma16816(acco[g * 2],     pl, vh);
                mma16816(acco[g * 2 + 1], pl, vh + 2);
            }
        }
        float* O = (float*)(sma + ATT_S);
        int orow = wid * 16 + (lid >> 2), ocol = (lid & 3) * 2;
        #pragma unroll
        for (int j = 0; j < 4; j++) {
            *(float2*)&O[orow * 36 + j * 8 + ocol]       = make_float2(acco[j][0], acco[j][1]);
            *(float2*)&O[(orow + 8) * 36 + j * 8 + ocol] = make_float2(acco[j][2], acco[j][3]);
        }
    }
    __syncthreads();

    // 5. store o[p<49][d<32] to scrambled-flat g_o
    size_t obase = (size_t)b * OB_PER_B + (size_t)h * (WS2 * NWIN * HDD) + (size_t)n * HDD;
    const float* O = (const float*)(sma + ATT_S);
    for (int idx = tid; idx < WS2 * 8; idx += 128) {
        int p = idx >> 3, d4 = (idx & 7) * 4;
        float4 v = *(const float4*)&O[p * 36 + d4];
        *(float4*)&g_o[obase + (size_t)p * (NWIN * HDD) + d4] = v;
    }
}

// -------- K4: conv reduce over scrambled s2 axis (float4) --------
__global__ void k_conv(const float* __restrict__ conv_w, const float* __restrict__ conv_b) {
    __shared__ float cw[WS2];
    int tid = threadIdx.x;
    if (tid < WS2) cw[tid] = conv_w[tid];
    __syncthreads();
    int idx = blockIdx.x * 256 + tid;                  // < 76800 (c4 granularity)
    int b = idx / (NWIN * 64);
    int r = idx - b * (NWIN * 64);
    int n2 = r >> 6, c4 = r & 63;
    size_t base = (size_t)b * OB_PER_B + (size_t)n2 * (WS2 * NC) + c4 * 4;
    float cb = conv_b[0];
    float4 acc = make_float4(cb, cb, cb, cb);
    #pragma unroll 7
    for (int s2 = 0; s2 < WS2; s2++) {
        float4 v = *(const float4*)&g_o[base + (size_t)s2 * NC];
        float w = cw[s2];
        acc.x += w * v.x; acc.y += w * v.y; acc.z += w * v.z; acc.w += w * v.w;
    }
    *(float4*)&g_ypre[(size_t)idx * 4] = acc;
}

// -------- K5a: transpose w_proj --------
__global__ void k_wpt(const float* __restrict__ wp) {
    int idx = blockIdx.x * 256 + threadIdx.x;          // < 65536
    int k = idx >> 8, c = idx & 255;
    g_wpT[idx] = wp[c * NC + k];
}

// -------- K5b: y = ypre @ w_proj^T + b_proj (8 rows/block) --------
#define PR 8
__global__ void __launch_bounds__(256) k_proj(const float* __restrict__ bp, float* __restrict__ out) {
    __shared__ float rowv[PR][NC];
    int row0 = blockIdx.x * PR;
    int tid = threadIdx.x;
    for (int i = tid; i < PR * NC; i += 256)
        rowv[i >> 8][i & 255] = g_ypre[(size_t)(row0 + (i >> 8)) * NC + (i & 255)];
    __syncthreads();
    int c = tid;
    float acc[PR];
    #pragma unroll
    for (int i = 0; i < PR; i++) acc[i] = 0.f;
    #pragma unroll 4
    for (int k = 0; k < NC; k++) {
        float wv = g_wpT[k * NC + c];
        #pragma unroll
        for (int i = 0; i < PR; i++) acc[i] += rowv[i][k] * wv;
    }
    float bb = bp[c];
    #pragma unroll
    for (int i = 0; i < PR; i++)
        out[(size_t)(row0 + i) * NC + c] = acc[i] + bb;
}

extern "C" void kernel_launch(void* const* d_in, const int* in_sizes, int n_in,
                              void* d_out, int out_size) {
    const float* x        = (const float*)d_in[0];
    const float* polys    = (const float*)d_in[1];
    const float* w_qkv    = (const float*)d_in[2];
    const float* b_qkv    = (const float*)d_in[3];
    const float* w_proj   = (const float*)d_in[4];
    const float* b_proj   = (const float*)d_in[5];
    const float* conv_w   = (const float*)d_in[6];
    const float* conv_b   = (const float*)d_in[7];
    const float* pos_bias = (const float*)d_in[8];
    float* out = (float*)d_out;

    static int smem_set = 0;
    if (!smem_set) {
        cudaFuncSetAttribute(k_gemm_mma, cudaFuncAttributeMaxDynamicSharedMemorySize, GSM_TOTAL);
        cudaFuncSetAttribute(k_attn_mma, cudaFuncAttributeMaxDynamicSharedMemorySize, ATT_SM);
        smem_set = 1;
    }

    dim3 gt(128, 8, 2);
    dim3 bt(32, 8);
    k_transpose_x<<<gt, bt>>>(x);
    k_sample<<<NROWS, 64>>>(polys);
    k_wfrag<<<(96 * 16 * 32) / 256, 256>>>(w_qkv);
    dim3 g2(MPAD / 128, NOUT3 / 128);
    k_gemm_mma<<<g2, 256, GSM_TOTAL>>>(b_qkv);
    k_attn_mma<<<NB * NHD * NWIN, 128, ATT_SM>>>(pos_bias);
    k_conv<<<(NB * NWIN * 64) / 256, 256>>>(conv_w, conv_b);
    k_wpt<<<NC * NC / 256, 256>>>(w_proj);
    k_proj<<<NB * NWIN / PR, 256>>>(b_proj, out);
}